// round 2
// baseline (speedup 1.0000x reference)
#include <cuda_runtime.h>
#include <math.h>

#define N_NODES 50000
#define N_EDGES 1600000
#define D_IN    256
#define D_OUT   64
#define D_HID   128   // 2*D_OUT, concat layout: [high(0..63) | low(64..127)]

#define ALPHA    0.2f
#define BT_SLOPE 0.01f

// ---------------- scratch (device globals; no cudaMalloc allowed) ----------------
__device__ float g_Wc[D_IN * D_HID];            // combined [256][128] weight
__device__ float g_H[N_NODES * D_HID];          // raw GEMM out, then activated in place
__device__ float g_s_high[N_NODES];
__device__ float g_s_low[N_NODES];
__device__ unsigned g_t_high, g_t_low, g_t_out; // float bits of global abs-max
__device__ int g_hist[N_NODES];
__device__ int g_row_start[N_NODES + 1];
__device__ int g_cursor[N_NODES];
__device__ int g_csr_dst[N_EDGES];
__device__ int g_edge_is64;

// ---------------- K_detect: is the edge buffer int64 or int32? ----------------
// If int64 node ids (< 2^31, non-negative), every odd int32 word is the zero
// high-half. If genuine int32 edges, odd words are node ids, ~never all zero.
__global__ void k_detect(const int* __restrict__ e32) {
    int v = e32[2 * threadIdx.x + 1];           // 256 odd words sampled
    int any = __syncthreads_or(v != 0);
    if (threadIdx.x == 0) g_edge_is64 = (any == 0) ? 1 : 0;
}

__device__ __forceinline__ int edge_at(const int* __restrict__ e32, long idx) {
    // idx in [0, 2*N_EDGES): element index of the logical int array
    return g_edge_is64 ? e32[idx * 2] : e32[idx];   // little-endian low word
}

// ---------------- K0: init ----------------
__global__ void k_init() {
    int i = blockIdx.x * blockDim.x + threadIdx.x;
    if (i < N_NODES) { g_hist[i] = 0; g_cursor[i] = 0; }
    if (i == 0) { g_t_high = 0u; g_t_low = 0u; g_t_out = 0u; }
}

// ---------------- K0b: build combined weight ----------------
__global__ void k_build_wc(const float* __restrict__ W_high,
                           const float* __restrict__ W_low) {
    int i = blockIdx.x * blockDim.x + threadIdx.x;   // 0 .. 256*128-1
    if (i >= D_IN * D_HID) return;
    int k = i / D_HID;
    int c = i % D_HID;
    g_Wc[i] = (c < D_OUT) ? W_high[k * D_OUT + c] : W_low[k * D_OUT + (c - D_OUT)];
}

// ---------------- K1: tiled SGEMM  H = input @ Wc, fused abs-max ----------------
#define BM 64
#define BN 64
#define BK 16
__global__ void k_gemm(const float* __restrict__ A) {
    __shared__ float As[BK][BM];   // As[k][m]
    __shared__ float Bs[BK][BN];   // Bs[k][n]
    __shared__ float red[256];

    int tid = threadIdx.x;          // 256 threads
    int tx = tid & 15;              // 0..15
    int ty = tid >> 4;              // 0..15
    int rowBase = blockIdx.y * BM;
    int colBase = blockIdx.x * BN;  // 0 or 64

    float acc[4][4];
    #pragma unroll
    for (int i = 0; i < 4; i++)
        #pragma unroll
        for (int j = 0; j < 4; j++) acc[i][j] = 0.f;

    int aRow = tid >> 2;            // 0..63
    int aCol = (tid & 3) * 4;       // 0,4,8,12
    int bRow = tid >> 4;            // 0..15
    int bCol = (tid & 15) * 4;      // 0..60

    for (int k0 = 0; k0 < D_IN; k0 += BK) {
        float4 av = make_float4(0.f, 0.f, 0.f, 0.f);
        int gr = rowBase + aRow;
        if (gr < N_NODES)
            av = *(const float4*)&A[(long)gr * D_IN + k0 + aCol];
        As[aCol + 0][aRow] = av.x;
        As[aCol + 1][aRow] = av.y;
        As[aCol + 2][aRow] = av.z;
        As[aCol + 3][aRow] = av.w;

        float4 bv = *(const float4*)&g_Wc[(k0 + bRow) * D_HID + colBase + bCol];
        *(float4*)&Bs[bRow][bCol] = bv;
        __syncthreads();

        #pragma unroll
        for (int k = 0; k < BK; k++) {
            float4 a4 = *(float4*)&As[k][ty * 4];
            float4 b4 = *(float4*)&Bs[k][tx * 4];
            float ar[4] = {a4.x, a4.y, a4.z, a4.w};
            float br[4] = {b4.x, b4.y, b4.z, b4.w};
            #pragma unroll
            for (int i = 0; i < 4; i++)
                #pragma unroll
                for (int j = 0; j < 4; j++)
                    acc[i][j] = fmaf(ar[i], br[j], acc[i][j]);
        }
        __syncthreads();
    }

    // epilogue: store raw H, block-reduce abs-max, one atomicMax per block
    float m = 0.f;
    #pragma unroll
    for (int i = 0; i < 4; i++) {
        int r = rowBase + ty * 4 + i;
        if (r < N_NODES) {
            float4 v = make_float4(acc[i][0], acc[i][1], acc[i][2], acc[i][3]);
            *(float4*)&g_H[(long)r * D_HID + colBase + tx * 4] = v;
            m = fmaxf(m, fmaxf(fmaxf(fabsf(v.x), fabsf(v.y)),
                               fmaxf(fabsf(v.z), fabsf(v.w))));
        }
    }
    red[tid] = m;
    __syncthreads();
    for (int s = 128; s > 0; s >>= 1) {
        if (tid < s) red[tid] = fmaxf(red[tid], red[tid + s]);
        __syncthreads();
    }
    if (tid == 0) {
        unsigned* tgt = (colBase < D_OUT) ? &g_t_high : &g_t_low;
        atomicMax(tgt, __float_as_uint(red[0]));
    }
}

// ---------------- K2: relu_bt activation in place + per-node scalar s = h.a ----------------
__global__ void k_act_s(const float* __restrict__ a_high,
                        const float* __restrict__ a_low) {
    int warp = (blockIdx.x * blockDim.x + threadIdx.x) >> 5;
    int lane = threadIdx.x & 31;
    if (warp >= N_NODES) return;
    bool isHigh = lane < 16;
    float t = __uint_as_float(isHigh ? g_t_high : g_t_low);

    float4 x = *(float4*)&g_H[(long)warp * D_HID + lane * 4];
    float4 y;
    y.x = fminf(x.x >= 0.f ? x.x : BT_SLOPE * x.x, t);
    y.y = fminf(x.y >= 0.f ? x.y : BT_SLOPE * x.y, t);
    y.z = fminf(x.z >= 0.f ? x.z : BT_SLOPE * x.z, t);
    y.w = fminf(x.w >= 0.f ? x.w : BT_SLOPE * x.w, t);
    *(float4*)&g_H[(long)warp * D_HID + lane * 4] = y;

    float4 a4 = isHigh ? *(const float4*)&a_high[lane * 4]
                       : *(const float4*)&a_low[(lane - 16) * 4];
    float dot = y.x * a4.x + y.y * a4.y + y.z * a4.z + y.w * a4.w;
    float ph = isHigh ? dot : 0.f;
    float pl = isHigh ? 0.f : dot;
    #pragma unroll
    for (int o = 16; o > 0; o >>= 1) {
        ph += __shfl_down_sync(0xffffffffu, ph, o);
        pl += __shfl_down_sync(0xffffffffu, pl, o);
    }
    if (lane == 0) { g_s_high[warp] = ph; g_s_low[warp] = pl; }
}

// ---------------- K3: histogram of src ----------------
__global__ void k_hist(const int* __restrict__ e32) {
    int e = blockIdx.x * blockDim.x + threadIdx.x;
    if (e >= N_EDGES) return;
    int src = edge_at(e32, e);
    if ((unsigned)src < (unsigned)N_NODES)
        atomicAdd(&g_hist[src], 1);
}

// ---------------- K4: single-block exclusive scan -> row_start ----------------
__global__ void k_scan() {
    __shared__ int sh[1024];
    __shared__ int carry_sh;
    int tid = threadIdx.x;
    if (tid == 0) { carry_sh = 0; g_row_start[0] = 0; }
    __syncthreads();
    for (int base = 0; base < N_NODES; base += 1024) {
        int i = base + tid;
        int v = (i < N_NODES) ? g_hist[i] : 0;
        sh[tid] = v;
        __syncthreads();
        for (int off = 1; off < 1024; off <<= 1) {
            int t = (tid >= off) ? sh[tid - off] : 0;
            __syncthreads();
            sh[tid] += t;
            __syncthreads();
        }
        if (i < N_NODES) g_row_start[i + 1] = carry_sh + sh[tid];
        __syncthreads();
        if (tid == 0) carry_sh += sh[1023];
        __syncthreads();
    }
}

// ---------------- K5: scatter edges into CSR by src ----------------
__global__ void k_scatter(const int* __restrict__ e32) {
    int e = blockIdx.x * blockDim.x + threadIdx.x;
    if (e >= N_EDGES) return;
    int src = edge_at(e32, e);
    int dst = edge_at(e32, (long)N_EDGES + e);
    if ((unsigned)src >= (unsigned)N_NODES) return;
    if ((unsigned)dst >= (unsigned)N_NODES) dst = 0;
    int pos = g_row_start[src] + atomicAdd(&g_cursor[src], 1);
    g_csr_dst[pos] = dst;
}

// ---------------- K6: warp-per-node aggregation (no float atomics) ----------------
__global__ void k_agg(float* __restrict__ out) {
    int warp = (blockIdx.x * blockDim.x + threadIdx.x) >> 5;
    int lane = threadIdx.x & 31;
    if (warp >= N_NODES) return;
    bool isHigh = lane < 16;

    int start = g_row_start[warp];
    int end   = g_row_start[warp + 1];
    float sh_n = g_s_high[warp];
    float sl_n = g_s_low[warp];

    float4 acc = make_float4(0.f, 0.f, 0.f, 0.f);
    float wsum_h = 0.f, wsum_l = 0.f;

    for (int j = start; j < end; j++) {
        int dst = g_csr_dst[j];                       // broadcast load
        float xh = sh_n - g_s_high[dst];
        float xl = sl_n + g_s_low[dst];
        float wh = expf(-(xh >= 0.f ? xh : ALPHA * xh));
        float wl = expf(-(xl >= 0.f ? xl : ALPHA * xl));
        wsum_h += wh;
        wsum_l += wl;
        float w = isHigh ? wh : wl;
        float4 v = *(const float4*)&g_H[(long)dst * D_HID + lane * 4];
        acc.x = fmaf(w, v.x, acc.x);
        acc.y = fmaf(w, v.y, acc.y);
        acc.z = fmaf(w, v.z, acc.z);
        acc.w = fmaf(w, v.w, acc.w);
    }

    float wsum = (isHigh ? wsum_h : wsum_l) + 1e-16f;
    float inv = 1.0f / wsum;
    float4 o = make_float4(acc.x * inv, acc.y * inv, acc.z * inv, acc.w * inv);
    *(float4*)&out[(long)warp * D_HID + lane * 4] = o;

    // warp-reduce abs-max for final relu_bt threshold
    float m = fmaxf(fmaxf(fabsf(o.x), fabsf(o.y)), fmaxf(fabsf(o.z), fabsf(o.w)));
    #pragma unroll
    for (int off = 16; off > 0; off >>= 1)
        m = fmaxf(m, __shfl_down_sync(0xffffffffu, m, off));
    if (lane == 0) atomicMax(&g_t_out, __float_as_uint(m));
}

// ---------------- K7: final relu_bt in place on d_out ----------------
__global__ void k_final(float* __restrict__ out) {
    int i = blockIdx.x * blockDim.x + threadIdx.x;
    if (i >= N_NODES * D_HID) return;
    float t = __uint_as_float(g_t_out);
    float x = out[i];
    float y = x >= 0.f ? x : BT_SLOPE * x;
    out[i] = fminf(y, t);
}

// ---------------- launch ----------------
extern "C" void kernel_launch(void* const* d_in, const int* in_sizes, int n_in,
                              void* d_out, int out_size) {
    const float* input  = (const float*)d_in[0];
    const int*   e32    = (const int*)d_in[1];     // int32 or int64 (detected)
    const float* W_high = (const float*)d_in[2];
    const float* W_low  = (const float*)d_in[3];
    const float* a_high = (const float*)d_in[4];
    const float* a_low  = (const float*)d_in[5];
    float* out = (float*)d_out;

    // K_detect: edge dtype
    k_detect<<<1, 256>>>(e32);
    // K0: init counters / maxima
    k_init<<<(N_NODES + 255) / 256, 256>>>();
    // K0b: combined weight
    k_build_wc<<<(D_IN * D_HID + 255) / 256, 256>>>(W_high, W_low);
    // K1: GEMM + per-half abs-max
    dim3 ggrid(D_HID / BN, (N_NODES + BM - 1) / BM);
    k_gemm<<<ggrid, 256>>>(input);
    // K2: activation + per-node scalars
    k_act_s<<<(N_NODES * 32 + 255) / 256, 256>>>(a_high, a_low);
    // K3-K5: CSR build
    k_hist<<<(N_EDGES + 255) / 256, 256>>>(e32);
    k_scan<<<1, 1024>>>();
    k_scatter<<<(N_EDGES + 255) / 256, 256>>>(e32);
    // K6: aggregation -> d_out (pre final activation)
    k_agg<<<(N_NODES * 32 + 255) / 256, 256>>>(out);
    // K7: final relu_bt
    k_final<<<(N_NODES * D_HID + 255) / 256, 256>>>(out);
}

// round 3
// speedup vs baseline: 1.0533x; 1.0533x over previous
#include <cuda_runtime.h>
#include <cuda_fp16.h>
#include <math.h>

#define N_NODES 50000
#define N_EDGES 1600000
#define D_IN    256
#define D_OUT   64
#define D_HID   128   // 2*D_OUT, concat layout: [high(0..63) | low(64..127)]

#define ALPHA    0.2f
#define BT_SLOPE 0.01f

// ---------------- scratch (device globals; no cudaMalloc allowed) ----------------
__device__ float g_Wc[D_IN * D_HID];            // combined [256][128] weight
__device__ float g_H[N_NODES * D_HID];          // fp32 H (activated in place)
__device__ uint2 g_Hh[N_NODES * 32];            // fp16 copy: 128 halves/node = 32 uint2
__device__ float g_s_high[N_NODES];
__device__ float g_s_low[N_NODES];
__device__ unsigned g_t_high, g_t_low, g_t_out; // float bits of global abs-max
__device__ int g_hist[N_NODES];
__device__ int g_row_start[N_NODES + 1];
__device__ int g_cursor[N_NODES];
__device__ int g_csr_dst[N_EDGES];
__device__ int g_edge_is64;

// ---------------- K_detect: is the edge buffer int64 or int32? ----------------
__global__ void k_detect(const int* __restrict__ e32) {
    int v = e32[2 * threadIdx.x + 1];           // 256 odd words sampled
    int any = __syncthreads_or(v != 0);
    if (threadIdx.x == 0) g_edge_is64 = (any == 0) ? 1 : 0;
}

__device__ __forceinline__ int edge_at(const int* __restrict__ e32, long idx) {
    return g_edge_is64 ? e32[idx * 2] : e32[idx];   // little-endian low word
}

// ---------------- K0: init ----------------
__global__ void k_init() {
    int i = blockIdx.x * blockDim.x + threadIdx.x;
    if (i < N_NODES) { g_hist[i] = 0; g_cursor[i] = 0; }
    if (i == 0) { g_t_high = 0u; g_t_low = 0u; g_t_out = 0u; }
}

// ---------------- K0b: build combined weight ----------------
__global__ void k_build_wc(const float* __restrict__ W_high,
                           const float* __restrict__ W_low) {
    int i = blockIdx.x * blockDim.x + threadIdx.x;   // 0 .. 256*128-1
    if (i >= D_IN * D_HID) return;
    int k = i / D_HID;
    int c = i % D_HID;
    g_Wc[i] = (c < D_OUT) ? W_high[k * D_OUT + c] : W_low[k * D_OUT + (c - D_OUT)];
}

// ---------------- K1: 128x128 register-blocked SGEMM, fused abs-max ----------------
#define BM 128
#define BN 128
#define BK 16
__global__ void __launch_bounds__(256, 2) k_gemm(const float* __restrict__ A) {
    __shared__ float As[BK][BM + 4];   // As[k][m], pad for bank spread
    __shared__ float Bs[BK][BN + 4];

    int tid = threadIdx.x;              // 256 threads
    int tx = tid & 15;                  // 0..15 -> cols tx*8..+7
    int ty = tid >> 4;                  // 0..15 -> rows ty*8..+7
    int rowBase = blockIdx.x * BM;

    float acc[8][8];
    #pragma unroll
    for (int i = 0; i < 8; i++)
        #pragma unroll
        for (int j = 0; j < 8; j++) acc[i][j] = 0.f;

    int aRow = tid >> 1;                // 0..127
    int aCol = (tid & 1) * 8;           // 0 or 8
    int bRow = tid >> 4;                // 0..15
    int bCol = (tid & 15) * 8;          // 0..120

    for (int k0 = 0; k0 < D_IN; k0 += BK) {
        // A: each thread 8 floats of one row -> transposed scalar stores
        float4 av0 = make_float4(0.f, 0.f, 0.f, 0.f), av1 = av0;
        int gr = rowBase + aRow;
        if (gr < N_NODES) {
            av0 = *(const float4*)&A[(long)gr * D_IN + k0 + aCol];
            av1 = *(const float4*)&A[(long)gr * D_IN + k0 + aCol + 4];
        }
        As[aCol + 0][aRow] = av0.x;
        As[aCol + 1][aRow] = av0.y;
        As[aCol + 2][aRow] = av0.z;
        As[aCol + 3][aRow] = av0.w;
        As[aCol + 4][aRow] = av1.x;
        As[aCol + 5][aRow] = av1.y;
        As[aCol + 6][aRow] = av1.z;
        As[aCol + 7][aRow] = av1.w;

        // B: each thread 8 floats of one k-row, direct float4 stores
        float4 bv0 = *(const float4*)&g_Wc[(k0 + bRow) * D_HID + bCol];
        float4 bv1 = *(const float4*)&g_Wc[(k0 + bRow) * D_HID + bCol + 4];
        *(float4*)&Bs[bRow][bCol]     = bv0;
        *(float4*)&Bs[bRow][bCol + 4] = bv1;
        __syncthreads();

        #pragma unroll
        for (int k = 0; k < BK; k++) {
            float4 a0 = *(float4*)&As[k][ty * 8];
            float4 a1 = *(float4*)&As[k][ty * 8 + 4];
            float4 b0 = *(float4*)&Bs[k][tx * 8];
            float4 b1 = *(float4*)&Bs[k][tx * 8 + 4];
            float ar[8] = {a0.x, a0.y, a0.z, a0.w, a1.x, a1.y, a1.z, a1.w};
            float br[8] = {b0.x, b0.y, b0.z, b0.w, b1.x, b1.y, b1.z, b1.w};
            #pragma unroll
            for (int i = 0; i < 8; i++)
                #pragma unroll
                for (int j = 0; j < 8; j++)
                    acc[i][j] = fmaf(ar[i], br[j], acc[i][j]);
        }
        __syncthreads();
    }

    // epilogue: store raw H, per-half abs-max (thread's cols all in one half)
    float m = 0.f;
    #pragma unroll
    for (int i = 0; i < 8; i++) {
        int r = rowBase + ty * 8 + i;
        if (r < N_NODES) {
            float4 v0 = make_float4(acc[i][0], acc[i][1], acc[i][2], acc[i][3]);
            float4 v1 = make_float4(acc[i][4], acc[i][5], acc[i][6], acc[i][7]);
            *(float4*)&g_H[(long)r * D_HID + tx * 8]     = v0;
            *(float4*)&g_H[(long)r * D_HID + tx * 8 + 4] = v1;
            m = fmaxf(m, fmaxf(fmaxf(fabsf(v0.x), fabsf(v0.y)),
                               fmaxf(fabsf(v0.z), fabsf(v0.w))));
            m = fmaxf(m, fmaxf(fmaxf(fabsf(v1.x), fabsf(v1.y)),
                               fmaxf(fabsf(v1.z), fabsf(v1.w))));
        }
    }
    // reduce high-half and low-half separately, reusing As/Bs as scratch
    float* redH = &As[0][0];
    float* redL = &Bs[0][0];
    redH[tid] = (tx < 8) ? m : 0.f;
    redL[tid] = (tx < 8) ? 0.f : m;
    __syncthreads();
    for (int s = 128; s > 0; s >>= 1) {
        if (tid < s) {
            redH[tid] = fmaxf(redH[tid], redH[tid + s]);
            redL[tid] = fmaxf(redL[tid], redL[tid + s]);
        }
        __syncthreads();
    }
    if (tid == 0) {
        atomicMax(&g_t_high, __float_as_uint(redH[0]));
        atomicMax(&g_t_low,  __float_as_uint(redL[0]));
    }
}

// ---------------- K2: relu_bt in place + fp16 copy + per-node scalar s = h.a ----------------
__global__ void k_act_s(const float* __restrict__ a_high,
                        const float* __restrict__ a_low) {
    int warp = (blockIdx.x * blockDim.x + threadIdx.x) >> 5;
    int lane = threadIdx.x & 31;
    if (warp >= N_NODES) return;
    bool isHigh = lane < 16;
    float t = __uint_as_float(isHigh ? g_t_high : g_t_low);

    float4 x = *(float4*)&g_H[(long)warp * D_HID + lane * 4];
    float4 y;
    y.x = fminf(x.x >= 0.f ? x.x : BT_SLOPE * x.x, t);
    y.y = fminf(x.y >= 0.f ? x.y : BT_SLOPE * x.y, t);
    y.z = fminf(x.z >= 0.f ? x.z : BT_SLOPE * x.z, t);
    y.w = fminf(x.w >= 0.f ? x.w : BT_SLOPE * x.w, t);
    *(float4*)&g_H[(long)warp * D_HID + lane * 4] = y;

    // fp16 copy for the gather kernel
    __half2 p0 = __floats2half2_rn(y.x, y.y);
    __half2 p1 = __floats2half2_rn(y.z, y.w);
    uint2 packed;
    packed.x = *(unsigned*)&p0;
    packed.y = *(unsigned*)&p1;
    g_Hh[warp * 32 + lane] = packed;

    float4 a4 = isHigh ? *(const float4*)&a_high[lane * 4]
                       : *(const float4*)&a_low[(lane - 16) * 4];
    float dot = y.x * a4.x + y.y * a4.y + y.z * a4.z + y.w * a4.w;
    float ph = isHigh ? dot : 0.f;
    float pl = isHigh ? 0.f : dot;
    #pragma unroll
    for (int o = 16; o > 0; o >>= 1) {
        ph += __shfl_down_sync(0xffffffffu, ph, o);
        pl += __shfl_down_sync(0xffffffffu, pl, o);
    }
    if (lane == 0) { g_s_high[warp] = ph; g_s_low[warp] = pl; }
}

// ---------------- K3: histogram of src ----------------
__global__ void k_hist(const int* __restrict__ e32) {
    int e = blockIdx.x * blockDim.x + threadIdx.x;
    if (e >= N_EDGES) return;
    int src = edge_at(e32, e);
    if ((unsigned)src < (unsigned)N_NODES)
        atomicAdd(&g_hist[src], 1);
}

// ---------------- K4: single-block shuffle scan -> row_start ----------------
__global__ void k_scan() {
    __shared__ int wsum[32];
    __shared__ int carry_sh;
    int tid = threadIdx.x, lane = tid & 31, wid = tid >> 5;
    if (tid == 0) { carry_sh = 0; g_row_start[0] = 0; }
    __syncthreads();
    for (int base = 0; base < N_NODES; base += 1024) {
        int i = base + tid;
        int v = (i < N_NODES) ? g_hist[i] : 0;
        int inc = v;
        #pragma unroll
        for (int o = 1; o < 32; o <<= 1) {
            int tv = __shfl_up_sync(0xffffffffu, inc, o);
            if (lane >= o) inc += tv;
        }
        if (lane == 31) wsum[wid] = inc;
        __syncthreads();
        if (wid == 0) {
            int s = wsum[lane];
            #pragma unroll
            for (int o = 1; o < 32; o <<= 1) {
                int tv = __shfl_up_sync(0xffffffffu, s, o);
                if (lane >= o) s += tv;
            }
            wsum[lane] = s;
        }
        __syncthreads();
        int warpbase = (wid == 0) ? 0 : wsum[wid - 1];
        int total = wsum[31];
        if (i < N_NODES) g_row_start[i + 1] = carry_sh + warpbase + inc;
        __syncthreads();
        if (tid == 0) carry_sh += total;
        __syncthreads();
    }
}

// ---------------- K5: scatter edges into CSR by src ----------------
__global__ void k_scatter(const int* __restrict__ e32) {
    int e = blockIdx.x * blockDim.x + threadIdx.x;
    if (e >= N_EDGES) return;
    int src = edge_at(e32, e);
    int dst = edge_at(e32, (long)N_EDGES + e);
    if ((unsigned)src >= (unsigned)N_NODES) return;
    if ((unsigned)dst >= (unsigned)N_NODES) dst = 0;
    int pos = g_row_start[src] + atomicAdd(&g_cursor[src], 1);
    g_csr_dst[pos] = dst;
}

// ---------------- K6: warp-per-node aggregation (fp16 gather, no float atomics) ----------------
__global__ void k_agg(float* __restrict__ out) {
    int warp = (blockIdx.x * blockDim.x + threadIdx.x) >> 5;
    int lane = threadIdx.x & 31;
    if (warp >= N_NODES) return;
    bool isHigh = lane < 16;

    int start = g_row_start[warp];
    int end   = g_row_start[warp + 1];
    float sh_n = g_s_high[warp];
    float sl_n = g_s_low[warp];

    float4 acc = make_float4(0.f, 0.f, 0.f, 0.f);
    float wsum_h = 0.f, wsum_l = 0.f;

    for (int j = start; j < end; j++) {
        int dst = g_csr_dst[j];                       // broadcast load
        float xh = sh_n - g_s_high[dst];
        float xl = sl_n + g_s_low[dst];
        float wh = __expf(-(xh >= 0.f ? xh : ALPHA * xh));
        float wl = __expf(-(xl >= 0.f ? xl : ALPHA * xl));
        wsum_h += wh;
        wsum_l += wl;
        float w = isHigh ? wh : wl;
        uint2 v = g_Hh[(long)dst * 32 + lane];
        __half2 h0 = *(__half2*)&v.x;
        __half2 h1 = *(__half2*)&v.y;
        float2 f0 = __half22float2(h0);
        float2 f1 = __half22float2(h1);
        acc.x = fmaf(w, f0.x, acc.x);
        acc.y = fmaf(w, f0.y, acc.y);
        acc.z = fmaf(w, f1.x, acc.z);
        acc.w = fmaf(w, f1.y, acc.w);
    }

    float wsum = (isHigh ? wsum_h : wsum_l) + 1e-16f;
    float inv = 1.0f / wsum;
    float4 o = make_float4(acc.x * inv, acc.y * inv, acc.z * inv, acc.w * inv);
    *(float4*)&out[(long)warp * D_HID + lane * 4] = o;

    float m = fmaxf(fmaxf(fabsf(o.x), fabsf(o.y)), fmaxf(fabsf(o.z), fabsf(o.w)));
    #pragma unroll
    for (int off = 16; off > 0; off >>= 1)
        m = fmaxf(m, __shfl_down_sync(0xffffffffu, m, off));
    if (lane == 0) atomicMax(&g_t_out, __float_as_uint(m));
}

// ---------------- K7: final relu_bt in place on d_out ----------------
__global__ void k_final(float* __restrict__ out) {
    int i = blockIdx.x * blockDim.x + threadIdx.x;
    if (i >= N_NODES * D_HID) return;
    float t = __uint_as_float(g_t_out);
    float x = out[i];
    float y = x >= 0.f ? x : BT_SLOPE * x;
    out[i] = fminf(y, t);
}

// ---------------- launch ----------------
extern "C" void kernel_launch(void* const* d_in, const int* in_sizes, int n_in,
                              void* d_out, int out_size) {
    const float* input  = (const float*)d_in[0];
    const int*   e32    = (const int*)d_in[1];     // int32 or int64 (detected)
    const float* W_high = (const float*)d_in[2];
    const float* W_low  = (const float*)d_in[3];
    const float* a_high = (const float*)d_in[4];
    const float* a_low  = (const float*)d_in[5];
    float* out = (float*)d_out;

    k_detect<<<1, 256>>>(e32);
    k_init<<<(N_NODES + 255) / 256, 256>>>();
    k_build_wc<<<(D_IN * D_HID + 255) / 256, 256>>>(W_high, W_low);
    k_gemm<<<(N_NODES + BM - 1) / BM, 256>>>(input);
    k_act_s<<<(N_NODES * 32 + 255) / 256, 256>>>(a_high, a_low);
    k_hist<<<(N_EDGES + 255) / 256, 256>>>(e32);
    k_scan<<<1, 1024>>>();
    k_scatter<<<(N_EDGES + 255) / 256, 256>>>(e32);
    k_agg<<<(N_NODES * 32 + 255) / 256, 256>>>(out);
    k_final<<<(N_NODES * D_HID + 255) / 256, 256>>>(out);
}

// round 4
// speedup vs baseline: 1.1210x; 1.0643x over previous
#include <cuda_runtime.h>
#include <cuda_fp16.h>
#include <math.h>

#define N_NODES 50000
#define N_EDGES 1600000
#define D_IN    256
#define D_OUT   64
#define D_HID   128   // 2*D_OUT, concat layout: [high(0..63) | low(64..127)]

#define ALPHA    0.2f
#define BT_SLOPE 0.01f

typedef unsigned long long ull;

// ---------------- scratch (device globals; no cudaMalloc allowed) ----------------
__device__ float g_Wc[D_IN * D_HID];            // combined [256][128] weight
__device__ float g_H[N_NODES * D_HID];          // fp32 H (activated in place)
__device__ uint2 g_Hh[N_NODES * 32];            // fp16 copy: 128 halves/node = 32 uint2
__device__ float g_s_high[N_NODES];
__device__ float g_s_low[N_NODES];
__device__ unsigned g_t_high, g_t_low, g_t_out; // float bits of global abs-max
__device__ int g_hist[N_NODES];
__device__ int g_row_start[N_NODES + 1];
__device__ int g_cursor[N_NODES];
__device__ int g_csr_dst[N_EDGES];
__device__ int g_edge_is64;

__device__ __forceinline__ ull ffma2(ull a, ull b, ull c) {
    ull d;
    asm("fma.rn.f32x2 %0, %1, %2, %3;" : "=l"(d) : "l"(a), "l"(b), "l"(c));
    return d;
}
__device__ __forceinline__ float2 unpack2(ull v) {
    float2 f;
    asm("mov.b64 {%0, %1}, %2;" : "=f"(f.x), "=f"(f.y) : "l"(v));
    return f;
}

// ---------------- K_detect: is the edge buffer int64 or int32? ----------------
__global__ void k_detect(const int* __restrict__ e32) {
    int v = e32[2 * threadIdx.x + 1];           // 256 odd words sampled
    int any = __syncthreads_or(v != 0);
    if (threadIdx.x == 0) g_edge_is64 = (any == 0) ? 1 : 0;
}

__device__ __forceinline__ int edge_at(const int* __restrict__ e32, long idx) {
    return g_edge_is64 ? e32[idx * 2] : e32[idx];   // little-endian low word
}

// ---------------- K0: init ----------------
__global__ void k_init() {
    int i = blockIdx.x * blockDim.x + threadIdx.x;
    if (i < N_NODES) { g_hist[i] = 0; g_cursor[i] = 0; }
    if (i == 0) { g_t_high = 0u; g_t_low = 0u; g_t_out = 0u; }
}

// ---------------- K0b: build combined weight ----------------
__global__ void k_build_wc(const float* __restrict__ W_high,
                           const float* __restrict__ W_low) {
    int i = blockIdx.x * blockDim.x + threadIdx.x;   // 0 .. 256*128-1
    if (i >= D_IN * D_HID) return;
    int k = i / D_HID;
    int c = i % D_HID;
    g_Wc[i] = (c < D_OUT) ? W_high[k * D_OUT + c] : W_low[k * D_OUT + (c - D_OUT)];
}

// ---------------- K1: 128x128 FFMA2 SGEMM, fused abs-max ----------------
// acc pairs along n (j): b-pairs natural from Bs; A stored duplicated in As2.
#define BM 128
#define BN 128
#define BK 16
#define AS2_LD (2 * BM + 4)   // floats per k-row of As2
#define BS_LD  (BN + 4)
__global__ void __launch_bounds__(256, 2) k_gemm(const float* __restrict__ A) {
    __shared__ float As2[BK][AS2_LD];   // (a,a) duplicated pairs, [k][2*m]
    __shared__ float Bs[BK][BS_LD];     // [k][n]

    int tid = threadIdx.x;              // 256 threads
    int tx = tid & 15;                  // cols tx*8 .. +7
    int ty = tid >> 4;                  // rows ty*8 .. +7
    int rowBase = blockIdx.x * BM;

    ull accp[8][4];                     // [i][jpair]
    #pragma unroll
    for (int i = 0; i < 8; i++)
        #pragma unroll
        for (int q = 0; q < 4; q++) accp[i][q] = 0ull;

    int aRow = tid >> 1;                // 0..127
    int aCol = (tid & 1) * 8;           // 0 or 8
    int bRow = tid >> 4;                // 0..15
    int bCol = (tid & 15) * 8;          // 0..120

    for (int k0 = 0; k0 < D_IN; k0 += BK) {
        // A: 8 floats of one row -> duplicated transposed stores
        float4 av0 = make_float4(0.f, 0.f, 0.f, 0.f), av1 = av0;
        int gr = rowBase + aRow;
        if (gr < N_NODES) {
            av0 = *(const float4*)&A[(long)gr * D_IN + k0 + aCol];
            av1 = *(const float4*)&A[(long)gr * D_IN + k0 + aCol + 4];
        }
        {
            float va[8] = {av0.x, av0.y, av0.z, av0.w, av1.x, av1.y, av1.z, av1.w};
            #pragma unroll
            for (int c = 0; c < 8; c++)
                *(float2*)&As2[aCol + c][aRow * 2] = make_float2(va[c], va[c]);
        }

        // B: 8 floats of one k-row, direct float4 stores
        float4 bv0 = *(const float4*)&g_Wc[(k0 + bRow) * D_HID + bCol];
        float4 bv1 = *(const float4*)&g_Wc[(k0 + bRow) * D_HID + bCol + 4];
        *(float4*)&Bs[bRow][bCol]     = bv0;
        *(float4*)&Bs[bRow][bCol + 4] = bv1;
        __syncthreads();

        #pragma unroll
        for (int k = 0; k < BK; k++) {
            // b: 4 j-pairs via two 128-bit loads
            ulonglong2 b01 = *(ulonglong2*)&Bs[k][tx * 8];
            ulonglong2 b23 = *(ulonglong2*)&Bs[k][tx * 8 + 4];
            ull bq[4] = {b01.x, b01.y, b23.x, b23.y};
            // a: 8 duplicated values via four 128-bit broadcast loads
            #pragma unroll
            for (int qq = 0; qq < 4; qq++) {
                ulonglong2 ad = *(ulonglong2*)&As2[k][(ty * 8 + 2 * qq) * 2];
                #pragma unroll
                for (int q = 0; q < 4; q++) {
                    accp[2 * qq][q]     = ffma2(ad.x, bq[q], accp[2 * qq][q]);
                    accp[2 * qq + 1][q] = ffma2(ad.y, bq[q], accp[2 * qq + 1][q]);
                }
            }
        }
        __syncthreads();
    }

    // epilogue: store raw H, per-half abs-max (thread's cols all in one half)
    float m = 0.f;
    #pragma unroll
    for (int i = 0; i < 8; i++) {
        int r = rowBase + ty * 8 + i;
        if (r < N_NODES) {
            float2 p0 = unpack2(accp[i][0]);
            float2 p1 = unpack2(accp[i][1]);
            float2 p2 = unpack2(accp[i][2]);
            float2 p3 = unpack2(accp[i][3]);
            float4 v0 = make_float4(p0.x, p0.y, p1.x, p1.y);
            float4 v1 = make_float4(p2.x, p2.y, p3.x, p3.y);
            *(float4*)&g_H[(long)r * D_HID + tx * 8]     = v0;
            *(float4*)&g_H[(long)r * D_HID + tx * 8 + 4] = v1;
            m = fmaxf(m, fmaxf(fmaxf(fabsf(v0.x), fabsf(v0.y)),
                               fmaxf(fabsf(v0.z), fabsf(v0.w))));
            m = fmaxf(m, fmaxf(fmaxf(fabsf(v1.x), fabsf(v1.y)),
                               fmaxf(fabsf(v1.z), fabsf(v1.w))));
        }
    }
    float* redH = &As2[0][0];
    float* redL = &Bs[0][0];
    redH[tid] = (tx < 8) ? m : 0.f;
    redL[tid] = (tx < 8) ? 0.f : m;
    __syncthreads();
    for (int s = 128; s > 0; s >>= 1) {
        if (tid < s) {
            redH[tid] = fmaxf(redH[tid], redH[tid + s]);
            redL[tid] = fmaxf(redL[tid], redL[tid + s]);
        }
        __syncthreads();
    }
    if (tid == 0) {
        atomicMax(&g_t_high, __float_as_uint(redH[0]));
        atomicMax(&g_t_low,  __float_as_uint(redL[0]));
    }
}

// ---------------- K2: relu_bt in place + fp16 copy + per-node scalar s = h.a ----------------
__global__ void k_act_s(const float* __restrict__ a_high,
                        const float* __restrict__ a_low) {
    int warp = (blockIdx.x * blockDim.x + threadIdx.x) >> 5;
    int lane = threadIdx.x & 31;
    if (warp >= N_NODES) return;
    bool isHigh = lane < 16;
    float t = __uint_as_float(isHigh ? g_t_high : g_t_low);

    float4 x = *(float4*)&g_H[(long)warp * D_HID + lane * 4];
    float4 y;
    y.x = fminf(x.x >= 0.f ? x.x : BT_SLOPE * x.x, t);
    y.y = fminf(x.y >= 0.f ? x.y : BT_SLOPE * x.y, t);
    y.z = fminf(x.z >= 0.f ? x.z : BT_SLOPE * x.z, t);
    y.w = fminf(x.w >= 0.f ? x.w : BT_SLOPE * x.w, t);
    *(float4*)&g_H[(long)warp * D_HID + lane * 4] = y;

    __half2 p0 = __floats2half2_rn(y.x, y.y);
    __half2 p1 = __floats2half2_rn(y.z, y.w);
    uint2 packed;
    packed.x = *(unsigned*)&p0;
    packed.y = *(unsigned*)&p1;
    g_Hh[warp * 32 + lane] = packed;

    float4 a4 = isHigh ? *(const float4*)&a_high[lane * 4]
                       : *(const float4*)&a_low[(lane - 16) * 4];
    float dot = y.x * a4.x + y.y * a4.y + y.z * a4.z + y.w * a4.w;
    float ph = isHigh ? dot : 0.f;
    float pl = isHigh ? 0.f : dot;
    #pragma unroll
    for (int o = 16; o > 0; o >>= 1) {
        ph += __shfl_down_sync(0xffffffffu, ph, o);
        pl += __shfl_down_sync(0xffffffffu, pl, o);
    }
    if (lane == 0) { g_s_high[warp] = ph; g_s_low[warp] = pl; }
}

// ---------------- K3: histogram of src ----------------
__global__ void k_hist(const int* __restrict__ e32) {
    int e = blockIdx.x * blockDim.x + threadIdx.x;
    if (e >= N_EDGES) return;
    int src = edge_at(e32, e);
    if ((unsigned)src < (unsigned)N_NODES)
        atomicAdd(&g_hist[src], 1);
}

// ---------------- K4: single-block shuffle scan -> row_start ----------------
__global__ void k_scan() {
    __shared__ int wsum[32];
    __shared__ int carry_sh;
    int tid = threadIdx.x, lane = tid & 31, wid = tid >> 5;
    if (tid == 0) { carry_sh = 0; g_row_start[0] = 0; }
    __syncthreads();
    for (int base = 0; base < N_NODES; base += 1024) {
        int i = base + tid;
        int v = (i < N_NODES) ? g_hist[i] : 0;
        int inc = v;
        #pragma unroll
        for (int o = 1; o < 32; o <<= 1) {
            int tv = __shfl_up_sync(0xffffffffu, inc, o);
            if (lane >= o) inc += tv;
        }
        if (lane == 31) wsum[wid] = inc;
        __syncthreads();
        if (wid == 0) {
            int s = wsum[lane];
            #pragma unroll
            for (int o = 1; o < 32; o <<= 1) {
                int tv = __shfl_up_sync(0xffffffffu, s, o);
                if (lane >= o) s += tv;
            }
            wsum[lane] = s;
        }
        __syncthreads();
        int warpbase = (wid == 0) ? 0 : wsum[wid - 1];
        int total = wsum[31];
        if (i < N_NODES) g_row_start[i + 1] = carry_sh + warpbase + inc;
        __syncthreads();
        if (tid == 0) carry_sh += total;
        __syncthreads();
    }
}

// ---------------- K5: scatter edges into CSR by src ----------------
__global__ void k_scatter(const int* __restrict__ e32) {
    int e = blockIdx.x * blockDim.x + threadIdx.x;
    if (e >= N_EDGES) return;
    int src = edge_at(e32, e);
    int dst = edge_at(e32, (long)N_EDGES + e);
    if ((unsigned)src >= (unsigned)N_NODES) return;
    if ((unsigned)dst >= (unsigned)N_NODES) dst = 0;
    int pos = g_row_start[src] + atomicAdd(&g_cursor[src], 1);
    g_csr_dst[pos] = dst;
}

// ---------------- K6: warp-per-node aggregation, 2-edge unroll ----------------
__global__ void k_agg(float* __restrict__ out) {
    int warp = (blockIdx.x * blockDim.x + threadIdx.x) >> 5;
    int lane = threadIdx.x & 31;
    if (warp >= N_NODES) return;
    bool isHigh = lane < 16;

    int start = g_row_start[warp];
    int end   = g_row_start[warp + 1];
    float sh_n = g_s_high[warp];
    float sl_n = g_s_low[warp];

    float4 acc = make_float4(0.f, 0.f, 0.f, 0.f);
    float wsum_h = 0.f, wsum_l = 0.f;

    int j = start;
    for (; j + 1 < end; j += 2) {
        int d0 = g_csr_dst[j];
        int d1 = g_csr_dst[j + 1];
        float sh0 = g_s_high[d0], sl0 = g_s_low[d0];
        float sh1 = g_s_high[d1], sl1 = g_s_low[d1];
        uint2 v0 = g_Hh[(long)d0 * 32 + lane];
        uint2 v1 = g_Hh[(long)d1 * 32 + lane];

        float xh0 = sh_n - sh0, xl0 = sl_n + sl0;
        float xh1 = sh_n - sh1, xl1 = sl_n + sl1;
        float wh0 = __expf(-(xh0 >= 0.f ? xh0 : ALPHA * xh0));
        float wl0 = __expf(-(xl0 >= 0.f ? xl0 : ALPHA * xl0));
        float wh1 = __expf(-(xh1 >= 0.f ? xh1 : ALPHA * xh1));
        float wl1 = __expf(-(xl1 >= 0.f ? xl1 : ALPHA * xl1));
        wsum_h += wh0 + wh1;
        wsum_l += wl0 + wl1;
        float w0 = isHigh ? wh0 : wl0;
        float w1 = isHigh ? wh1 : wl1;

        float2 f0 = __half22float2(*(__half2*)&v0.x);
        float2 f1 = __half22float2(*(__half2*)&v0.y);
        float2 g0 = __half22float2(*(__half2*)&v1.x);
        float2 g1 = __half22float2(*(__half2*)&v1.y);
        acc.x = fmaf(w0, f0.x, fmaf(w1, g0.x, acc.x));
        acc.y = fmaf(w0, f0.y, fmaf(w1, g0.y, acc.y));
        acc.z = fmaf(w0, f1.x, fmaf(w1, g1.x, acc.z));
        acc.w = fmaf(w0, f1.y, fmaf(w1, g1.y, acc.w));
    }
    if (j < end) {
        int d0 = g_csr_dst[j];
        float xh = sh_n - g_s_high[d0];
        float xl = sl_n + g_s_low[d0];
        float wh = __expf(-(xh >= 0.f ? xh : ALPHA * xh));
        float wl = __expf(-(xl >= 0.f ? xl : ALPHA * xl));
        wsum_h += wh;
        wsum_l += wl;
        float w = isHigh ? wh : wl;
        uint2 v = g_Hh[(long)d0 * 32 + lane];
        float2 f0 = __half22float2(*(__half2*)&v.x);
        float2 f1 = __half22float2(*(__half2*)&v.y);
        acc.x = fmaf(w, f0.x, acc.x);
        acc.y = fmaf(w, f0.y, acc.y);
        acc.z = fmaf(w, f1.x, acc.z);
        acc.w = fmaf(w, f1.y, acc.w);
    }

    float wsum = (isHigh ? wsum_h : wsum_l) + 1e-16f;
    float inv = 1.0f / wsum;
    float4 o = make_float4(acc.x * inv, acc.y * inv, acc.z * inv, acc.w * inv);
    *(float4*)&out[(long)warp * D_HID + lane * 4] = o;

    float m = fmaxf(fmaxf(fabsf(o.x), fabsf(o.y)), fmaxf(fabsf(o.z), fabsf(o.w)));
    #pragma unroll
    for (int off = 16; off > 0; off >>= 1)
        m = fmaxf(m, __shfl_down_sync(0xffffffffu, m, off));
    if (lane == 0) atomicMax(&g_t_out, __float_as_uint(m));
}

// ---------------- K7: final relu_bt in place on d_out ----------------
__global__ void k_final(float* __restrict__ out) {
    int i = blockIdx.x * blockDim.x + threadIdx.x;
    if (i >= N_NODES * D_HID) return;
    float t = __uint_as_float(g_t_out);
    float x = out[i];
    float y = x >= 0.f ? x : BT_SLOPE * x;
    out[i] = fminf(y, t);
}

// ---------------- launch ----------------
extern "C" void kernel_launch(void* const* d_in, const int* in_sizes, int n_in,
                              void* d_out, int out_size) {
    const float* input  = (const float*)d_in[0];
    const int*   e32    = (const int*)d_in[1];     // int32 or int64 (detected)
    const float* W_high = (const float*)d_in[2];
    const float* W_low  = (const float*)d_in[3];
    const float* a_high = (const float*)d_in[4];
    const float* a_low  = (const float*)d_in[5];
    float* out = (float*)d_out;

    k_detect<<<1, 256>>>(e32);
    k_init<<<(N_NODES + 255) / 256, 256>>>();
    k_build_wc<<<(D_IN * D_HID + 255) / 256, 256>>>(W_high, W_low);
    k_gemm<<<(N_NODES + BM - 1) / BM, 256>>>(input);
    k_act_s<<<(N_NODES * 32 + 255) / 256, 256>>>(a_high, a_low);
    k_hist<<<(N_EDGES + 255) / 256, 256>>>(e32);
    k_scan<<<1, 1024>>>();
    k_scatter<<<(N_EDGES + 255) / 256, 256>>>(e32);
    k_agg<<<(N_NODES * 32 + 255) / 256, 256>>>(out);
    k_final<<<(N_NODES * D_HID + 255) / 256, 256>>>(out);
}

// round 5
// speedup vs baseline: 1.2047x; 1.0747x over previous
#include <cuda_runtime.h>
#include <cuda_fp16.h>
#include <mma.h>
#include <math.h>

using namespace nvcuda;

#define N_NODES 50000
#define N_EDGES 1600000
#define D_IN    256
#define D_OUT   64
#define D_HID   128   // 2*D_OUT, concat layout: [high(0..63) | low(64..127)]

#define ALPHA    0.2f
#define BT_SLOPE 0.01f

// ---------------- scratch (device globals; no cudaMalloc allowed) ----------------
__device__ float g_Wc[D_IN * D_HID];              // combined [256][128] weight
__device__ float g_H[(N_NODES + 64) * D_HID];     // fp32 H (+64 pad rows for wmma tail stores)
__device__ uint2 g_Hh[N_NODES * 32];              // fp16 copy: 128 halves/node
__device__ float g_s_high[N_NODES];
__device__ float g_s_low[N_NODES];
__device__ unsigned g_t_high, g_t_low, g_t_out;   // float bits of global abs-max
__device__ int g_hist[N_NODES];
__device__ int g_row_start[N_NODES + 1];
__device__ int g_cursor[N_NODES];
__device__ int g_csr_dst[N_EDGES];
__device__ int g_edge_is64;

// ---------------- K_detect: is the edge buffer int64 or int32? ----------------
__global__ void k_detect(const int* __restrict__ e32) {
    int v = e32[2 * threadIdx.x + 1];           // 256 odd words sampled
    int any = __syncthreads_or(v != 0);
    if (threadIdx.x == 0) g_edge_is64 = (any == 0) ? 1 : 0;
}

__device__ __forceinline__ int edge_at(const int* __restrict__ e32, long idx) {
    return g_edge_is64 ? e32[idx * 2] : e32[idx];   // little-endian low word
}

// ---------------- K0: init ----------------
__global__ void k_init() {
    int i = blockIdx.x * blockDim.x + threadIdx.x;
    if (i < N_NODES) { g_hist[i] = 0; g_cursor[i] = 0; }
    if (i == 0) { g_t_high = 0u; g_t_low = 0u; g_t_out = 0u; }
}

// ---------------- K0b: build combined weight ----------------
__global__ void k_build_wc(const float* __restrict__ W_high,
                           const float* __restrict__ W_low) {
    int i = blockIdx.x * blockDim.x + threadIdx.x;   // 0 .. 256*128-1
    if (i >= D_IN * D_HID) return;
    int k = i / D_HID;
    int c = i % D_HID;
    g_Wc[i] = (c < D_OUT) ? W_high[k * D_OUT + c] : W_low[k * D_OUT + (c - D_OUT)];
}

// ---------------- K1: TF32 WMMA GEMM  H = input @ Wc, fused abs-max ----------------
// block tile 64x128, 8 warps as 4(row) x 2(col), each warp 16x64 via 4 frags
#define GBM 64
#define GBK 32
#define AS_LD 36
#define BS_LD 132
__global__ void __launch_bounds__(256, 2) k_gemm(const float* __restrict__ A) {
    __shared__ float As[GBM][AS_LD];     // [m][k]
    __shared__ float Bs[GBK][BS_LD];     // [k][n]
    __shared__ float redH[8], redL[8];

    int tid = threadIdx.x;
    int lane = tid & 31;
    int wid = tid >> 5;
    int warp_row = wid & 3;              // 0..3 -> rows warp_row*16
    int warp_col = wid >> 2;             // 0..1 -> cols warp_col*64
    int rowBase = blockIdx.x * GBM;

    wmma::fragment<wmma::accumulator, 16, 16, 8, float> acc[4];
    #pragma unroll
    for (int q = 0; q < 4; q++) wmma::fill_fragment(acc[q], 0.0f);

    int aRow = tid >> 2;                 // 0..63
    int aCol = (tid & 3) * 8;            // 0,8,16,24
    int bRow = tid >> 3;                 // 0..31
    int bCol = (tid & 7) * 16;           // 0..112

    for (int k0 = 0; k0 < D_IN; k0 += GBK) {
        float4 av0 = make_float4(0.f, 0.f, 0.f, 0.f), av1 = av0;
        int gr = rowBase + aRow;
        if (gr < N_NODES) {
            av0 = *(const float4*)&A[(long)gr * D_IN + k0 + aCol];
            av1 = *(const float4*)&A[(long)gr * D_IN + k0 + aCol + 4];
        }
        *(float4*)&As[aRow][aCol]     = av0;
        *(float4*)&As[aRow][aCol + 4] = av1;

        #pragma unroll
        for (int q = 0; q < 4; q++) {
            float4 bv = *(const float4*)&g_Wc[(k0 + bRow) * D_HID + bCol + q * 4];
            *(float4*)&Bs[bRow][bCol + q * 4] = bv;
        }
        __syncthreads();

        #pragma unroll
        for (int kk = 0; kk < GBK; kk += 8) {
            wmma::fragment<wmma::matrix_a, 16, 16, 8, wmma::precision::tf32, wmma::row_major> af;
            wmma::load_matrix_sync(af, &As[warp_row * 16][kk], AS_LD);
            #pragma unroll
            for (int i = 0; i < af.num_elements; i++)
                af.x[i] = wmma::__float_to_tf32(af.x[i]);
            #pragma unroll
            for (int q = 0; q < 4; q++) {
                wmma::fragment<wmma::matrix_b, 16, 16, 8, wmma::precision::tf32, wmma::row_major> bf;
                wmma::load_matrix_sync(bf, &Bs[kk][warp_col * 64 + q * 16], BS_LD);
                #pragma unroll
                for (int i = 0; i < bf.num_elements; i++)
                    bf.x[i] = wmma::__float_to_tf32(bf.x[i]);
                wmma::mma_sync(acc[q], af, bf, acc[q]);
            }
        }
        __syncthreads();
    }

    // epilogue: store tile (pad rows absorb tail overflow), abs-max from fragments
    int outRow = rowBase + warp_row * 16;
    float m = 0.f;
    #pragma unroll
    for (int q = 0; q < 4; q++) {
        int col = warp_col * 64 + q * 16;
        wmma::store_matrix_sync(&g_H[(long)outRow * D_HID + col], acc[q],
                                D_HID, wmma::mem_row_major);
        #pragma unroll
        for (int i = 0; i < acc[q].num_elements; i++)
            m = fmaxf(m, fabsf(acc[q].x[i]));   // OOB rows are exact zeros
    }
    #pragma unroll
    for (int o = 16; o > 0; o >>= 1)
        m = fmaxf(m, __shfl_down_sync(0xffffffffu, m, o));
    if (lane == 0) {
        redH[wid] = (warp_col == 0) ? m : 0.f;
        redL[wid] = (warp_col == 0) ? 0.f : m;
    }
    __syncthreads();
    if (tid == 0) {
        float mh = 0.f, ml = 0.f;
        #pragma unroll
        for (int w = 0; w < 8; w++) { mh = fmaxf(mh, redH[w]); ml = fmaxf(ml, redL[w]); }
        atomicMax(&g_t_high, __float_as_uint(mh));
        atomicMax(&g_t_low,  __float_as_uint(ml));
    }
}

// ---------------- K2: relu_bt in place + fp16 copy + per-node scalar s = h.a ----------------
__global__ void k_act_s(const float* __restrict__ a_high,
                        const float* __restrict__ a_low) {
    int warp = (blockIdx.x * blockDim.x + threadIdx.x) >> 5;
    int lane = threadIdx.x & 31;
    if (warp >= N_NODES) return;
    bool isHigh = lane < 16;
    float t = __uint_as_float(isHigh ? g_t_high : g_t_low);

    float4 x = *(float4*)&g_H[(long)warp * D_HID + lane * 4];
    float4 y;
    y.x = fminf(x.x >= 0.f ? x.x : BT_SLOPE * x.x, t);
    y.y = fminf(x.y >= 0.f ? x.y : BT_SLOPE * x.y, t);
    y.z = fminf(x.z >= 0.f ? x.z : BT_SLOPE * x.z, t);
    y.w = fminf(x.w >= 0.f ? x.w : BT_SLOPE * x.w, t);
    *(float4*)&g_H[(long)warp * D_HID + lane * 4] = y;

    __half2 p0 = __floats2half2_rn(y.x, y.y);
    __half2 p1 = __floats2half2_rn(y.z, y.w);
    uint2 packed;
    packed.x = *(unsigned*)&p0;
    packed.y = *(unsigned*)&p1;
    g_Hh[warp * 32 + lane] = packed;

    float4 a4 = isHigh ? *(const float4*)&a_high[lane * 4]
                       : *(const float4*)&a_low[(lane - 16) * 4];
    float dot = y.x * a4.x + y.y * a4.y + y.z * a4.z + y.w * a4.w;
    float ph = isHigh ? dot : 0.f;
    float pl = isHigh ? 0.f : dot;
    #pragma unroll
    for (int o = 16; o > 0; o >>= 1) {
        ph += __shfl_down_sync(0xffffffffu, ph, o);
        pl += __shfl_down_sync(0xffffffffu, pl, o);
    }
    if (lane == 0) { g_s_high[warp] = ph; g_s_low[warp] = pl; }
}

// ---------------- K3: histogram of src ----------------
__global__ void k_hist(const int* __restrict__ e32) {
    int e = blockIdx.x * blockDim.x + threadIdx.x;
    if (e >= N_EDGES) return;
    int src = edge_at(e32, e);
    if ((unsigned)src < (unsigned)N_NODES)
        atomicAdd(&g_hist[src], 1);
}

// ---------------- K4: single-block shuffle scan -> row_start ----------------
__global__ void k_scan() {
    __shared__ int wsum[32];
    __shared__ int carry_sh;
    int tid = threadIdx.x, lane = tid & 31, wid = tid >> 5;
    if (tid == 0) { carry_sh = 0; g_row_start[0] = 0; }
    __syncthreads();
    for (int base = 0; base < N_NODES; base += 1024) {
        int i = base + tid;
        int v = (i < N_NODES) ? g_hist[i] : 0;
        int inc = v;
        #pragma unroll
        for (int o = 1; o < 32; o <<= 1) {
            int tv = __shfl_up_sync(0xffffffffu, inc, o);
            if (lane >= o) inc += tv;
        }
        if (lane == 31) wsum[wid] = inc;
        __syncthreads();
        if (wid == 0) {
            int s = wsum[lane];
            #pragma unroll
            for (int o = 1; o < 32; o <<= 1) {
                int tv = __shfl_up_sync(0xffffffffu, s, o);
                if (lane >= o) s += tv;
            }
            wsum[lane] = s;
        }
        __syncthreads();
        int warpbase = (wid == 0) ? 0 : wsum[wid - 1];
        int total = wsum[31];
        if (i < N_NODES) g_row_start[i + 1] = carry_sh + warpbase + inc;
        __syncthreads();
        if (tid == 0) carry_sh += total;
        __syncthreads();
    }
}

// ---------------- K5: scatter edges into CSR by src ----------------
__global__ void k_scatter(const int* __restrict__ e32) {
    int e = blockIdx.x * blockDim.x + threadIdx.x;
    if (e >= N_EDGES) return;
    int src = edge_at(e32, e);
    int dst = edge_at(e32, (long)N_EDGES + e);
    if ((unsigned)src >= (unsigned)N_NODES) return;
    if ((unsigned)dst >= (unsigned)N_NODES) dst = 0;
    int pos = g_row_start[src] + atomicAdd(&g_cursor[src], 1);
    g_csr_dst[pos] = dst;
}

// ---------------- K6: warp-per-node aggregation, 2-edge unroll ----------------
__global__ void k_agg(float* __restrict__ out) {
    int warp = (blockIdx.x * blockDim.x + threadIdx.x) >> 5;
    int lane = threadIdx.x & 31;
    if (warp >= N_NODES) return;
    bool isHigh = lane < 16;

    int start = g_row_start[warp];
    int end   = g_row_start[warp + 1];
    float sh_n = g_s_high[warp];
    float sl_n = g_s_low[warp];

    float4 acc = make_float4(0.f, 0.f, 0.f, 0.f);
    float wsum_h = 0.f, wsum_l = 0.f;

    int j = start;
    for (; j + 1 < end; j += 2) {
        int d0 = g_csr_dst[j];
        int d1 = g_csr_dst[j + 1];
        float sh0 = g_s_high[d0], sl0 = g_s_low[d0];
        float sh1 = g_s_high[d1], sl1 = g_s_low[d1];
        uint2 v0 = g_Hh[(long)d0 * 32 + lane];
        uint2 v1 = g_Hh[(long)d1 * 32 + lane];

        float xh0 = sh_n - sh0, xl0 = sl_n + sl0;
        float xh1 = sh_n - sh1, xl1 = sl_n + sl1;
        float wh0 = __expf(-(xh0 >= 0.f ? xh0 : ALPHA * xh0));
        float wl0 = __expf(-(xl0 >= 0.f ? xl0 : ALPHA * xl0));
        float wh1 = __expf(-(xh1 >= 0.f ? xh1 : ALPHA * xh1));
        float wl1 = __expf(-(xl1 >= 0.f ? xl1 : ALPHA * xl1));
        wsum_h += wh0 + wh1;
        wsum_l += wl0 + wl1;
        float w0 = isHigh ? wh0 : wl0;
        float w1 = isHigh ? wh1 : wl1;

        float2 f0 = __half22float2(*(__half2*)&v0.x);
        float2 f1 = __half22float2(*(__half2*)&v0.y);
        float2 g0 = __half22float2(*(__half2*)&v1.x);
        float2 g1 = __half22float2(*(__half2*)&v1.y);
        acc.x = fmaf(w0, f0.x, fmaf(w1, g0.x, acc.x));
        acc.y = fmaf(w0, f0.y, fmaf(w1, g0.y, acc.y));
        acc.z = fmaf(w0, f1.x, fmaf(w1, g1.x, acc.z));
        acc.w = fmaf(w0, f1.y, fmaf(w1, g1.y, acc.w));
    }
    if (j < end) {
        int d0 = g_csr_dst[j];
        float xh = sh_n - g_s_high[d0];
        float xl = sl_n + g_s_low[d0];
        float wh = __expf(-(xh >= 0.f ? xh : ALPHA * xh));
        float wl = __expf(-(xl >= 0.f ? xl : ALPHA * xl));
        wsum_h += wh;
        wsum_l += wl;
        float w = isHigh ? wh : wl;
        uint2 v = g_Hh[(long)d0 * 32 + lane];
        float2 f0 = __half22float2(*(__half2*)&v.x);
        float2 f1 = __half22float2(*(__half2*)&v.y);
        acc.x = fmaf(w, f0.x, acc.x);
        acc.y = fmaf(w, f0.y, acc.y);
        acc.z = fmaf(w, f1.x, acc.z);
        acc.w = fmaf(w, f1.y, acc.w);
    }

    float wsum = (isHigh ? wsum_h : wsum_l) + 1e-16f;
    float inv = 1.0f / wsum;
    float4 o = make_float4(acc.x * inv, acc.y * inv, acc.z * inv, acc.w * inv);
    *(float4*)&out[(long)warp * D_HID + lane * 4] = o;

    float m = fmaxf(fmaxf(fabsf(o.x), fabsf(o.y)), fmaxf(fabsf(o.z), fabsf(o.w)));
    #pragma unroll
    for (int off = 16; off > 0; off >>= 1)
        m = fmaxf(m, __shfl_down_sync(0xffffffffu, m, off));
    if (lane == 0) atomicMax(&g_t_out, __float_as_uint(m));
}

// ---------------- K7: final relu_bt in place on d_out ----------------
__global__ void k_final(float* __restrict__ out) {
    int i = blockIdx.x * blockDim.x + threadIdx.x;
    if (i >= N_NODES * D_HID) return;
    float t = __uint_as_float(g_t_out);
    float x = out[i];
    float y = x >= 0.f ? x : BT_SLOPE * x;
    out[i] = fminf(y, t);
}

// ---------------- launch ----------------
extern "C" void kernel_launch(void* const* d_in, const int* in_sizes, int n_in,
                              void* d_out, int out_size) {
    const float* input  = (const float*)d_in[0];
    const int*   e32    = (const int*)d_in[1];     // int32 or int64 (detected)
    const float* W_high = (const float*)d_in[2];
    const float* W_low  = (const float*)d_in[3];
    const float* a_high = (const float*)d_in[4];
    const float* a_low  = (const float*)d_in[5];
    float* out = (float*)d_out;

    k_detect<<<1, 256>>>(e32);
    k_init<<<(N_NODES + 255) / 256, 256>>>();
    k_build_wc<<<(D_IN * D_HID + 255) / 256, 256>>>(W_high, W_low);
    k_gemm<<<(N_NODES + GBM - 1) / GBM, 256>>>(input);
    k_act_s<<<(N_NODES * 32 + 255) / 256, 256>>>(a_high, a_low);
    k_hist<<<(N_EDGES + 255) / 256, 256>>>(e32);
    k_scan<<<1, 1024>>>();
    k_scatter<<<(N_EDGES + 255) / 256, 256>>>(e32);
    k_agg<<<(N_NODES * 32 + 255) / 256, 256>>>(out);
    k_final<<<(N_NODES * D_HID + 255) / 256, 256>>>(out);
}

// round 6
// speedup vs baseline: 1.5567x; 1.2921x over previous
#include <cuda_runtime.h>
#include <cuda_fp16.h>
#include <mma.h>
#include <math.h>

using namespace nvcuda;

#define N_NODES 50000
#define N_EDGES 1600000
#define D_IN    256
#define D_OUT   64
#define D_HID   128   // 2*D_OUT, concat layout: [high(0..63) | low(64..127)]

#define ALPHA    0.2f
#define BT_SLOPE 0.01f

#define NB_SCAN 49    // ceil(50000/1024)

// ---------------- scratch (device globals; no cudaMalloc allowed) ----------------
__device__ float g_Wc[D_IN * D_HID];              // combined [256][128] weight, tf32-rounded
__device__ float g_H[(N_NODES + 64) * D_HID];     // fp32 H (+64 pad rows for wmma tail stores)
__device__ uint2 g_Hh[N_NODES * 32];              // fp16 copy: 128 halves/node
__device__ float g_s_high[N_NODES];
__device__ float g_s_low[N_NODES];
__device__ unsigned g_t_high, g_t_low, g_t_out;   // float bits of global abs-max
__device__ int g_hist[N_NODES];
__device__ int g_scan_local[N_NODES];             // inclusive scan within 1024-tile
__device__ int g_blocksum[64];
__device__ int g_blockpref[64];                   // exclusive scan of block sums
__device__ int g_cursor[N_NODES];
__device__ int g_csr_dst[N_EDGES];
__device__ int g_edge_is64;

__device__ __forceinline__ void cp_async16(void* sptr, const void* gptr) {
    unsigned saddr = (unsigned)__cvta_generic_to_shared(sptr);
    asm volatile("cp.async.cg.shared.global [%0], [%1], 16;" :: "r"(saddr), "l"(gptr));
}

__device__ __forceinline__ int edge_at(const int* __restrict__ e32, long idx) {
    return g_edge_is64 ? e32[idx * 2] : e32[idx];   // little-endian low word
}

// exclusive prefix of hist at i (i in [0, N_NODES])
__device__ __forceinline__ int row_start_at(int i) {
    if (i == 0) return 0;
    int j = i - 1;
    return g_blockpref[j >> 10] + g_scan_local[j];
}

// ---------------- K_setup: detect edge dtype + init + build Wc (tf32-rounded) ----------------
__global__ void k_setup(const int* __restrict__ e32,
                        const float* __restrict__ W_high,
                        const float* __restrict__ W_low) {
    int i = blockIdx.x * blockDim.x + threadIdx.x;
    if (blockIdx.x == 0) {
        int v = e32[2 * threadIdx.x + 1];       // 256 odd words sampled
        int any = __syncthreads_or(v != 0);
        if (threadIdx.x == 0) {
            g_edge_is64 = (any == 0) ? 1 : 0;
            g_t_high = 0u; g_t_low = 0u; g_t_out = 0u;
        }
    }
    if (i < N_NODES) { g_hist[i] = 0; g_cursor[i] = 0; }
    if (i < D_IN * D_HID) {
        int k = i / D_HID;
        int c = i % D_HID;
        float v = (c < D_OUT) ? W_high[k * D_OUT + c] : W_low[k * D_OUT + (c - D_OUT)];
        g_Wc[i] = wmma::__float_to_tf32(v);     // pre-round B once
    }
}

// ---------------- K1: TF32 WMMA GEMM, cp.async double-buffered ----------------
// block tile 64x128, 8 warps as 4(row) x 2(col), each warp 16x64 via 4 frags
#define GBM 64
#define GBK 16
#define AS_LD 20    // 16 + 4 pad (80 B rows, 16B-aligned)
#define BS_LD 132   // 128 + 4 pad (528 B rows, 16B-aligned)
#define KITERS (D_IN / GBK)
__global__ void __launch_bounds__(256, 2) k_gemm(const float* __restrict__ A) {
    __shared__ float As[2][GBM][AS_LD];
    __shared__ float Bs[2][GBK][BS_LD];
    __shared__ float redH[8], redL[8];

    int tid = threadIdx.x;
    int lane = tid & 31;
    int wid = tid >> 5;
    int warp_row = wid & 3;              // rows warp_row*16
    int warp_col = wid >> 2;             // cols warp_col*64
    int rowBase = blockIdx.x * GBM;

    wmma::fragment<wmma::accumulator, 16, 16, 8, float> acc[4];
    #pragma unroll
    for (int q = 0; q < 4; q++) wmma::fill_fragment(acc[q], 0.0f);

    int aRow = tid >> 2;                 // 0..63
    int aCol = (tid & 3) * 4;            // 0,4,8,12
    int bRow = tid >> 4;                 // 0..15
    int bCol = (tid & 15) * 8;           // 0..120
    int gr = rowBase + aRow;
    bool aOK = gr < N_NODES;
    const float* aSrc = &A[(long)gr * D_IN + aCol];

    // stage tile 0
    {
        if (aOK) cp_async16(&As[0][aRow][aCol], aSrc);
        else     *(float4*)&As[0][aRow][aCol] = make_float4(0.f, 0.f, 0.f, 0.f);
        cp_async16(&Bs[0][bRow][bCol],     &g_Wc[bRow * D_HID + bCol]);
        cp_async16(&Bs[0][bRow][bCol + 4], &g_Wc[bRow * D_HID + bCol + 4]);
        asm volatile("cp.async.commit_group;");
    }

    for (int it = 0; it < KITERS; it++) {
        int buf = it & 1;
        if (it + 1 < KITERS) {
            int k0 = (it + 1) * GBK;
            int nb = buf ^ 1;
            if (aOK) cp_async16(&As[nb][aRow][aCol], aSrc + k0);
            else     *(float4*)&As[nb][aRow][aCol] = make_float4(0.f, 0.f, 0.f, 0.f);
            cp_async16(&Bs[nb][bRow][bCol],     &g_Wc[(k0 + bRow) * D_HID + bCol]);
            cp_async16(&Bs[nb][bRow][bCol + 4], &g_Wc[(k0 + bRow) * D_HID + bCol + 4]);
            asm volatile("cp.async.commit_group;");
            asm volatile("cp.async.wait_group 1;");
        } else {
            asm volatile("cp.async.wait_group 0;");
        }
        __syncthreads();

        #pragma unroll
        for (int kk = 0; kk < GBK; kk += 8) {
            wmma::fragment<wmma::matrix_a, 16, 16, 8, wmma::precision::tf32, wmma::row_major> af;
            wmma::load_matrix_sync(af, &As[buf][warp_row * 16][kk], AS_LD);
            #pragma unroll
            for (int i = 0; i < af.num_elements; i++)
                af.x[i] = wmma::__float_to_tf32(af.x[i]);
            #pragma unroll
            for (int q = 0; q < 4; q++) {
                wmma::fragment<wmma::matrix_b, 16, 16, 8, wmma::precision::tf32, wmma::row_major> bf;
                wmma::load_matrix_sync(bf, &Bs[buf][kk][warp_col * 64 + q * 16], BS_LD);
                // Bs already tf32-rounded at setup; no conversion needed
                wmma::mma_sync(acc[q], af, bf, acc[q]);
            }
        }
        __syncthreads();
    }

    // epilogue: store tile (pad rows absorb tail overflow), abs-max from fragments
    int outRow = rowBase + warp_row * 16;
    float m = 0.f;
    #pragma unroll
    for (int q = 0; q < 4; q++) {
        int col = warp_col * 64 + q * 16;
        wmma::store_matrix_sync(&g_H[(long)outRow * D_HID + col], acc[q],
                                D_HID, wmma::mem_row_major);
        #pragma unroll
        for (int i = 0; i < acc[q].num_elements; i++)
            m = fmaxf(m, fabsf(acc[q].x[i]));   // OOB rows are exact zeros
    }
    #pragma unroll
    for (int o = 16; o > 0; o >>= 1)
        m = fmaxf(m, __shfl_down_sync(0xffffffffu, m, o));
    if (lane == 0) {
        redH[wid] = (warp_col == 0) ? m : 0.f;
        redL[wid] = (warp_col == 0) ? 0.f : m;
    }
    __syncthreads();
    if (tid == 0) {
        float mh = 0.f, ml = 0.f;
        #pragma unroll
        for (int w = 0; w < 8; w++) { mh = fmaxf(mh, redH[w]); ml = fmaxf(ml, redL[w]); }
        atomicMax(&g_t_high, __float_as_uint(mh));
        atomicMax(&g_t_low,  __float_as_uint(ml));
    }
}

// ---------------- K2: relu_bt in place + fp16 copy + per-node scalar s = h.a ----------------
__global__ void k_act_s(const float* __restrict__ a_high,
                        const float* __restrict__ a_low) {
    int warp = (blockIdx.x * blockDim.x + threadIdx.x) >> 5;
    int lane = threadIdx.x & 31;
    if (warp >= N_NODES) return;
    bool isHigh = lane < 16;
    float t = __uint_as_float(isHigh ? g_t_high : g_t_low);

    float4 x = *(float4*)&g_H[(long)warp * D_HID + lane * 4];
    float4 y;
    y.x = fminf(x.x >= 0.f ? x.x : BT_SLOPE * x.x, t);
    y.y = fminf(x.y >= 0.f ? x.y : BT_SLOPE * x.y, t);
    y.z = fminf(x.z >= 0.f ? x.z : BT_SLOPE * x.z, t);
    y.w = fminf(x.w >= 0.f ? x.w : BT_SLOPE * x.w, t);
    *(float4*)&g_H[(long)warp * D_HID + lane * 4] = y;

    __half2 p0 = __floats2half2_rn(y.x, y.y);
    __half2 p1 = __floats2half2_rn(y.z, y.w);
    uint2 packed;
    packed.x = *(unsigned*)&p0;
    packed.y = *(unsigned*)&p1;
    g_Hh[warp * 32 + lane] = packed;

    float4 a4 = isHigh ? *(const float4*)&a_high[lane * 4]
                       : *(const float4*)&a_low[(lane - 16) * 4];
    float dot = y.x * a4.x + y.y * a4.y + y.z * a4.z + y.w * a4.w;
    float ph = isHigh ? dot : 0.f;
    float pl = isHigh ? 0.f : dot;
    #pragma unroll
    for (int o = 16; o > 0; o >>= 1) {
        ph += __shfl_down_sync(0xffffffffu, ph, o);
        pl += __shfl_down_sync(0xffffffffu, pl, o);
    }
    if (lane == 0) { g_s_high[warp] = ph; g_s_low[warp] = pl; }
}

// ---------------- K3: histogram of src ----------------
__global__ void k_hist(const int* __restrict__ e32) {
    int e = blockIdx.x * blockDim.x + threadIdx.x;
    if (e >= N_EDGES) return;
    int src = edge_at(e32, e);
    if ((unsigned)src < (unsigned)N_NODES)
        atomicAdd(&g_hist[src], 1);
}

// ---------------- K4a: per-1024-tile inclusive scan ----------------
__global__ void k_scan1() {
    __shared__ int wsum[32];
    int tid = threadIdx.x, lane = tid & 31, wid = tid >> 5;
    int i = blockIdx.x * 1024 + tid;
    int v = (i < N_NODES) ? g_hist[i] : 0;
    int inc = v;
    #pragma unroll
    for (int o = 1; o < 32; o <<= 1) {
        int tv = __shfl_up_sync(0xffffffffu, inc, o);
        if (lane >= o) inc += tv;
    }
    if (lane == 31) wsum[wid] = inc;
    __syncthreads();
    if (wid == 0) {
        int s = wsum[lane];
        #pragma unroll
        for (int o = 1; o < 32; o <<= 1) {
            int tv = __shfl_up_sync(0xffffffffu, s, o);
            if (lane >= o) s += tv;
        }
        wsum[lane] = s;
    }
    __syncthreads();
    int incl = inc + ((wid == 0) ? 0 : wsum[wid - 1]);
    if (i < N_NODES) g_scan_local[i] = incl;
    if (tid == 1023) g_blocksum[blockIdx.x] = incl;
}

// ---------------- K4b: scan 49 block sums (1 warp, 2 elems/lane) ----------------
__global__ void k_scan2() {
    int lane = threadIdx.x;
    int v0 = (2 * lane < NB_SCAN)     ? g_blocksum[2 * lane]     : 0;
    int v1 = (2 * lane + 1 < NB_SCAN) ? g_blocksum[2 * lane + 1] : 0;
    int p = v0 + v1;
    int inc = p;
    #pragma unroll
    for (int o = 1; o < 32; o <<= 1) {
        int tv = __shfl_up_sync(0xffffffffu, inc, o);
        if (lane >= o) inc += tv;
    }
    int excl = inc - p;
    if (2 * lane < NB_SCAN)     g_blockpref[2 * lane]     = excl;
    if (2 * lane + 1 < NB_SCAN) g_blockpref[2 * lane + 1] = excl + v0;
}

// ---------------- K5: scatter edges into CSR by src ----------------
__global__ void k_scatter(const int* __restrict__ e32) {
    int e = blockIdx.x * blockDim.x + threadIdx.x;
    if (e >= N_EDGES) return;
    int src = edge_at(e32, e);
    int dst = edge_at(e32, (long)N_EDGES + e);
    if ((unsigned)src >= (unsigned)N_NODES) return;
    if ((unsigned)dst >= (unsigned)N_NODES) dst = 0;
    int pos = row_start_at(src) + atomicAdd(&g_cursor[src], 1);
    g_csr_dst[pos] = dst;
}

// ---------------- K6: warp-per-node aggregation, 4-edge unroll ----------------
__global__ void k_agg(float* __restrict__ out) {
    int warp = (blockIdx.x * blockDim.x + threadIdx.x) >> 5;
    int lane = threadIdx.x & 31;
    if (warp >= N_NODES) return;
    bool isHigh = lane < 16;

    int start = row_start_at(warp);
    int end   = row_start_at(warp + 1);
    float sh_n = g_s_high[warp];
    float sl_n = g_s_low[warp];

    float4 acc = make_float4(0.f, 0.f, 0.f, 0.f);
    float wsum_h = 0.f, wsum_l = 0.f;

    int j = start;
    for (; j + 3 < end; j += 4) {
        int d[4];
        float shd[4], sld[4];
        uint2 v[4];
        #pragma unroll
        for (int r = 0; r < 4; r++) d[r] = g_csr_dst[j + r];
        #pragma unroll
        for (int r = 0; r < 4; r++) {
            shd[r] = g_s_high[d[r]];
            sld[r] = g_s_low[d[r]];
            v[r] = g_Hh[(long)d[r] * 32 + lane];
        }
        #pragma unroll
        for (int r = 0; r < 4; r++) {
            float xh = sh_n - shd[r];
            float xl = sl_n + sld[r];
            float wh = __expf(-(xh >= 0.f ? xh : ALPHA * xh));
            float wl = __expf(-(xl >= 0.f ? xl : ALPHA * xl));
            wsum_h += wh;
            wsum_l += wl;
            float w = isHigh ? wh : wl;
            float2 f0 = __half22float2(*(__half2*)&v[r].x);
            float2 f1 = __half22float2(*(__half2*)&v[r].y);
            acc.x = fmaf(w, f0.x, acc.x);
            acc.y = fmaf(w, f0.y, acc.y);
            acc.z = fmaf(w, f1.x, acc.z);
            acc.w = fmaf(w, f1.y, acc.w);
        }
    }
    for (; j < end; j++) {
        int d0 = g_csr_dst[j];
        float xh = sh_n - g_s_high[d0];
        float xl = sl_n + g_s_low[d0];
        float wh = __expf(-(xh >= 0.f ? xh : ALPHA * xh));
        float wl = __expf(-(xl >= 0.f ? xl : ALPHA * xl));
        wsum_h += wh;
        wsum_l += wl;
        float w = isHigh ? wh : wl;
        uint2 v = g_Hh[(long)d0 * 32 + lane];
        float2 f0 = __half22float2(*(__half2*)&v.x);
        float2 f1 = __half22float2(*(__half2*)&v.y);
        acc.x = fmaf(w, f0.x, acc.x);
        acc.y = fmaf(w, f0.y, acc.y);
        acc.z = fmaf(w, f1.x, acc.z);
        acc.w = fmaf(w, f1.y, acc.w);
    }

    float wsum = (isHigh ? wsum_h : wsum_l) + 1e-16f;
    float inv = 1.0f / wsum;
    float4 o = make_float4(acc.x * inv, acc.y * inv, acc.z * inv, acc.w * inv);
    *(float4*)&out[(long)warp * D_HID + lane * 4] = o;

    float m = fmaxf(fmaxf(fabsf(o.x), fabsf(o.y)), fmaxf(fabsf(o.z), fabsf(o.w)));
    #pragma unroll
    for (int off = 16; off > 0; off >>= 1)
        m = fmaxf(m, __shfl_down_sync(0xffffffffu, m, off));
    if (lane == 0) atomicMax(&g_t_out, __float_as_uint(m));
}

// ---------------- K7: final relu_bt in place on d_out ----------------
__global__ void k_final(float* __restrict__ out) {
    int i = blockIdx.x * blockDim.x + threadIdx.x;
    if (i >= N_NODES * D_HID) return;
    float t = __uint_as_float(g_t_out);
    float x = out[i];
    float y = x >= 0.f ? x : BT_SLOPE * x;
    out[i] = fminf(y, t);
}

// ---------------- launch ----------------
extern "C" void kernel_launch(void* const* d_in, const int* in_sizes, int n_in,
                              void* d_out, int out_size) {
    const float* input  = (const float*)d_in[0];
    const int*   e32    = (const int*)d_in[1];     // int32 or int64 (detected)
    const float* W_high = (const float*)d_in[2];
    const float* W_low  = (const float*)d_in[3];
    const float* a_high = (const float*)d_in[4];
    const float* a_low  = (const float*)d_in[5];
    float* out = (float*)d_out;

    k_setup<<<(N_NODES + 255) / 256, 256>>>(e32, W_high, W_low);
    k_gemm<<<(N_NODES + GBM - 1) / GBM, 256>>>(input);
    k_act_s<<<(N_NODES * 32 + 255) / 256, 256>>>(a_high, a_low);
    k_hist<<<(N_EDGES + 255) / 256, 256>>>(e32);
    k_scan1<<<NB_SCAN, 1024>>>();
    k_scan2<<<1, 32>>>();
    k_scatter<<<(N_EDGES + 255) / 256, 256>>>(e32);
    k_agg<<<(N_NODES * 32 + 255) / 256, 256>>>(out);
    k_final<<<(N_NODES * D_HID + 255) / 256, 256>>>(out);
}

// round 7
// speedup vs baseline: 1.7383x; 1.1167x over previous
#include <cuda_runtime.h>
#include <cuda_fp16.h>
#include <mma.h>
#include <math.h>

using namespace nvcuda;

#define N_NODES 50000
#define N_EDGES 1600000
#define D_IN    256
#define D_OUT   64
#define D_HID   128   // 2*D_OUT, concat layout: [high(0..63) | low(64..127)]

#define ALPHA    0.2f
#define BT_SLOPE 0.01f

#define NB_SCAN 49    // ceil(50000/1024)

// ---------------- scratch (device globals; no cudaMalloc allowed) ----------------
__device__ float g_Wc[D_IN * D_HID];              // combined [256][128] weight, tf32-rounded
__device__ float g_H[(N_NODES + 64) * D_HID];     // fp32 H (+64 pad rows for wmma tail stores)
__device__ uint2 g_Hh[N_NODES * 32];              // fp16 copy: 128 halves/node
__device__ float g_s_high[N_NODES];
__device__ float g_s_low[N_NODES];
__device__ unsigned g_t_high, g_t_low, g_t_out;   // float bits of global abs-max
__device__ int g_hist[N_NODES];
__device__ int g_scan_local[N_NODES];             // inclusive scan within 1024-tile
__device__ int g_blocksum[64];
__device__ int g_blockpref[64];                   // exclusive scan of block sums
__device__ int g_cursor[N_NODES];
__device__ int g_csr_dst[N_EDGES];
__device__ int g_edge_is64;

__device__ __forceinline__ void cp_async16(void* sptr, const void* gptr) {
    unsigned saddr = (unsigned)__cvta_generic_to_shared(sptr);
    asm volatile("cp.async.cg.shared.global [%0], [%1], 16;" :: "r"(saddr), "l"(gptr));
}

// exclusive prefix of hist at i (i in [0, N_NODES])
__device__ __forceinline__ int row_start_at(int i) {
    if (i == 0) return 0;
    int j = i - 1;
    return g_blockpref[j >> 10] + g_scan_local[j];
}

// ---------------- K_setup: detect edge dtype + init + build Wc (tf32-rounded) ----------------
__global__ void k_setup(const int* __restrict__ e32,
                        const float* __restrict__ W_high,
                        const float* __restrict__ W_low) {
    int i = blockIdx.x * blockDim.x + threadIdx.x;
    if (blockIdx.x == 0) {
        int v = e32[2 * threadIdx.x + 1];       // 256 odd words sampled
        int any = __syncthreads_or(v != 0);
        if (threadIdx.x == 0) {
            g_edge_is64 = (any == 0) ? 1 : 0;
            g_t_high = 0u; g_t_low = 0u; g_t_out = 0u;
        }
    }
    if (i < N_NODES) { g_hist[i] = 0; g_cursor[i] = 0; }
    if (i < D_IN * D_HID) {
        int k = i / D_HID;
        int c = i % D_HID;
        float v = (c < D_OUT) ? W_high[k * D_OUT + c] : W_low[k * D_OUT + (c - D_OUT)];
        g_Wc[i] = wmma::__float_to_tf32(v);     // pre-round B once
    }
}

// ---------------- K1: TF32 WMMA GEMM, cp.async double-buffered ----------------
#define GBM 64
#define GBK 16
#define AS_LD 20
#define BS_LD 132
#define KITERS (D_IN / GBK)
__global__ void __launch_bounds__(256, 2) k_gemm(const float* __restrict__ A) {
    __shared__ float As[2][GBM][AS_LD];
    __shared__ float Bs[2][GBK][BS_LD];
    __shared__ float redH[8], redL[8];

    int tid = threadIdx.x;
    int lane = tid & 31;
    int wid = tid >> 5;
    int warp_row = wid & 3;
    int warp_col = wid >> 2;
    int rowBase = blockIdx.x * GBM;

    wmma::fragment<wmma::accumulator, 16, 16, 8, float> acc[4];
    #pragma unroll
    for (int q = 0; q < 4; q++) wmma::fill_fragment(acc[q], 0.0f);

    int aRow = tid >> 2;
    int aCol = (tid & 3) * 4;
    int bRow = tid >> 4;
    int bCol = (tid & 15) * 8;
    int gr = rowBase + aRow;
    bool aOK = gr < N_NODES;
    const float* aSrc = &A[(long)gr * D_IN + aCol];

    {
        if (aOK) cp_async16(&As[0][aRow][aCol], aSrc);
        else     *(float4*)&As[0][aRow][aCol] = make_float4(0.f, 0.f, 0.f, 0.f);
        cp_async16(&Bs[0][bRow][bCol],     &g_Wc[bRow * D_HID + bCol]);
        cp_async16(&Bs[0][bRow][bCol + 4], &g_Wc[bRow * D_HID + bCol + 4]);
        asm volatile("cp.async.commit_group;");
    }

    for (int it = 0; it < KITERS; it++) {
        int buf = it & 1;
        if (it + 1 < KITERS) {
            int k0 = (it + 1) * GBK;
            int nb = buf ^ 1;
            if (aOK) cp_async16(&As[nb][aRow][aCol], aSrc + k0);
            else     *(float4*)&As[nb][aRow][aCol] = make_float4(0.f, 0.f, 0.f, 0.f);
            cp_async16(&Bs[nb][bRow][bCol],     &g_Wc[(k0 + bRow) * D_HID + bCol]);
            cp_async16(&Bs[nb][bRow][bCol + 4], &g_Wc[(k0 + bRow) * D_HID + bCol + 4]);
            asm volatile("cp.async.commit_group;");
            asm volatile("cp.async.wait_group 1;");
        } else {
            asm volatile("cp.async.wait_group 0;");
        }
        __syncthreads();

        #pragma unroll
        for (int kk = 0; kk < GBK; kk += 8) {
            wmma::fragment<wmma::matrix_a, 16, 16, 8, wmma::precision::tf32, wmma::row_major> af;
            wmma::load_matrix_sync(af, &As[buf][warp_row * 16][kk], AS_LD);
            #pragma unroll
            for (int i = 0; i < af.num_elements; i++)
                af.x[i] = wmma::__float_to_tf32(af.x[i]);
            #pragma unroll
            for (int q = 0; q < 4; q++) {
                wmma::fragment<wmma::matrix_b, 16, 16, 8, wmma::precision::tf32, wmma::row_major> bf;
                wmma::load_matrix_sync(bf, &Bs[buf][kk][warp_col * 64 + q * 16], BS_LD);
                wmma::mma_sync(acc[q], af, bf, acc[q]);
            }
        }
        __syncthreads();
    }

    int outRow = rowBase + warp_row * 16;
    float m = 0.f;
    #pragma unroll
    for (int q = 0; q < 4; q++) {
        int col = warp_col * 64 + q * 16;
        wmma::store_matrix_sync(&g_H[(long)outRow * D_HID + col], acc[q],
                                D_HID, wmma::mem_row_major);
        #pragma unroll
        for (int i = 0; i < acc[q].num_elements; i++)
            m = fmaxf(m, fabsf(acc[q].x[i]));
    }
    #pragma unroll
    for (int o = 16; o > 0; o >>= 1)
        m = fmaxf(m, __shfl_down_sync(0xffffffffu, m, o));
    if (lane == 0) {
        redH[wid] = (warp_col == 0) ? m : 0.f;
        redL[wid] = (warp_col == 0) ? 0.f : m;
    }
    __syncthreads();
    if (tid == 0) {
        float mh = 0.f, ml = 0.f;
        #pragma unroll
        for (int w = 0; w < 8; w++) { mh = fmaxf(mh, redH[w]); ml = fmaxf(ml, redL[w]); }
        atomicMax(&g_t_high, __float_as_uint(mh));
        atomicMax(&g_t_low,  __float_as_uint(ml));
    }
}

// ---------------- K2: relu_bt in place + fp16 copy + per-node scalar s = h.a ----------------
__global__ void k_act_s(const float* __restrict__ a_high,
                        const float* __restrict__ a_low) {
    int warp = (blockIdx.x * blockDim.x + threadIdx.x) >> 5;
    int lane = threadIdx.x & 31;
    if (warp >= N_NODES) return;
    bool isHigh = lane < 16;
    float t = __uint_as_float(isHigh ? g_t_high : g_t_low);

    float4 x = *(float4*)&g_H[(long)warp * D_HID + lane * 4];
    float4 y;
    y.x = fminf(x.x >= 0.f ? x.x : BT_SLOPE * x.x, t);
    y.y = fminf(x.y >= 0.f ? x.y : BT_SLOPE * x.y, t);
    y.z = fminf(x.z >= 0.f ? x.z : BT_SLOPE * x.z, t);
    y.w = fminf(x.w >= 0.f ? x.w : BT_SLOPE * x.w, t);
    *(float4*)&g_H[(long)warp * D_HID + lane * 4] = y;

    __half2 p0 = __floats2half2_rn(y.x, y.y);
    __half2 p1 = __floats2half2_rn(y.z, y.w);
    uint2 packed;
    packed.x = *(unsigned*)&p0;
    packed.y = *(unsigned*)&p1;
    g_Hh[warp * 32 + lane] = packed;

    float4 a4 = isHigh ? *(const float4*)&a_high[lane * 4]
                       : *(const float4*)&a_low[(lane - 16) * 4];
    float dot = y.x * a4.x + y.y * a4.y + y.z * a4.z + y.w * a4.w;
    float ph = isHigh ? dot : 0.f;
    float pl = isHigh ? 0.f : dot;
    #pragma unroll
    for (int o = 16; o > 0; o >>= 1) {
        ph += __shfl_down_sync(0xffffffffu, ph, o);
        pl += __shfl_down_sync(0xffffffffu, pl, o);
    }
    if (lane == 0) { g_s_high[warp] = ph; g_s_low[warp] = pl; }
}

// ---------------- K3: histogram of src, 4 edges/thread ----------------
__global__ void k_hist(const int* __restrict__ e32) {
    int base = (blockIdx.x * blockDim.x + threadIdx.x) * 4;
    if (base >= N_EDGES) return;                    // N_EDGES % 4 == 0
    int s[4];
    if (g_edge_is64) {
        int4 a = *(const int4*)&e32[(long)base * 2];
        int4 b = *(const int4*)&e32[(long)base * 2 + 4];
        s[0] = a.x; s[1] = a.z; s[2] = b.x; s[3] = b.z;
    } else {
        int4 a = *(const int4*)&e32[base];
        s[0] = a.x; s[1] = a.y; s[2] = a.z; s[3] = a.w;
    }
    #pragma unroll
    for (int r = 0; r < 4; r++)
        if ((unsigned)s[r] < (unsigned)N_NODES)
            atomicAdd(&g_hist[s[r]], 1);
}

// ---------------- K4a: per-1024-tile inclusive scan ----------------
__global__ void k_scan1() {
    __shared__ int wsum[32];
    int tid = threadIdx.x, lane = tid & 31, wid = tid >> 5;
    int i = blockIdx.x * 1024 + tid;
    int v = (i < N_NODES) ? g_hist[i] : 0;
    int inc = v;
    #pragma unroll
    for (int o = 1; o < 32; o <<= 1) {
        int tv = __shfl_up_sync(0xffffffffu, inc, o);
        if (lane >= o) inc += tv;
    }
    if (lane == 31) wsum[wid] = inc;
    __syncthreads();
    if (wid == 0) {
        int s = wsum[lane];
        #pragma unroll
        for (int o = 1; o < 32; o <<= 1) {
            int tv = __shfl_up_sync(0xffffffffu, s, o);
            if (lane >= o) s += tv;
        }
        wsum[lane] = s;
    }
    __syncthreads();
    int incl = inc + ((wid == 0) ? 0 : wsum[wid - 1]);
    if (i < N_NODES) g_scan_local[i] = incl;
    if (tid == 1023) g_blocksum[blockIdx.x] = incl;
}

// ---------------- K4b: scan 49 block sums (1 warp, 2 elems/lane) ----------------
__global__ void k_scan2() {
    int lane = threadIdx.x;
    int v0 = (2 * lane < NB_SCAN)     ? g_blocksum[2 * lane]     : 0;
    int v1 = (2 * lane + 1 < NB_SCAN) ? g_blocksum[2 * lane + 1] : 0;
    int p = v0 + v1;
    int inc = p;
    #pragma unroll
    for (int o = 1; o < 32; o <<= 1) {
        int tv = __shfl_up_sync(0xffffffffu, inc, o);
        if (lane >= o) inc += tv;
    }
    int excl = inc - p;
    if (2 * lane < NB_SCAN)     g_blockpref[2 * lane]     = excl;
    if (2 * lane + 1 < NB_SCAN) g_blockpref[2 * lane + 1] = excl + v0;
}

// ---------------- K5: scatter edges into CSR by src, 2 edges/thread ----------------
__global__ void k_scatter(const int* __restrict__ e32) {
    int base = (blockIdx.x * blockDim.x + threadIdx.x) * 2;
    if (base >= N_EDGES) return;                    // N_EDGES % 2 == 0
    int s0, s1, d0, d1;
    if (g_edge_is64) {
        int4 a = *(const int4*)&e32[(long)base * 2];
        int4 b = *(const int4*)&e32[((long)N_EDGES + base) * 2];
        s0 = a.x; s1 = a.z; d0 = b.x; d1 = b.z;
    } else {
        int2 a = *(const int2*)&e32[base];
        int2 b = *(const int2*)&e32[N_EDGES + base];
        s0 = a.x; s1 = a.y; d0 = b.x; d1 = b.y;
    }
    if ((unsigned)s0 < (unsigned)N_NODES) {
        if ((unsigned)d0 >= (unsigned)N_NODES) d0 = 0;
        int pos = row_start_at(s0) + atomicAdd(&g_cursor[s0], 1);
        g_csr_dst[pos] = d0;
    }
    if ((unsigned)s1 < (unsigned)N_NODES) {
        if ((unsigned)d1 >= (unsigned)N_NODES) d1 = 0;
        int pos = row_start_at(s1) + atomicAdd(&g_cursor[s1], 1);
        g_csr_dst[pos] = d1;
    }
}

// ---------------- K6: warp-per-node aggregation, 4-edge unroll ----------------
__global__ void k_agg(float* __restrict__ out) {
    int warp = (blockIdx.x * blockDim.x + threadIdx.x) >> 5;
    int lane = threadIdx.x & 31;
    if (warp >= N_NODES) return;
    bool isHigh = lane < 16;

    int start = row_start_at(warp);
    int end   = row_start_at(warp + 1);
    float sh_n = g_s_high[warp];
    float sl_n = g_s_low[warp];

    float4 acc = make_float4(0.f, 0.f, 0.f, 0.f);
    float wsum_h = 0.f, wsum_l = 0.f;

    int j = start;
    for (; j + 3 < end; j += 4) {
        int d[4];
        float shd[4], sld[4];
        uint2 v[4];
        #pragma unroll
        for (int r = 0; r < 4; r++) d[r] = g_csr_dst[j + r];
        #pragma unroll
        for (int r = 0; r < 4; r++) {
            shd[r] = g_s_high[d[r]];
            sld[r] = g_s_low[d[r]];
            v[r] = g_Hh[(long)d[r] * 32 + lane];
        }
        #pragma unroll
        for (int r = 0; r < 4; r++) {
            float xh = sh_n - shd[r];
            float xl = sl_n + sld[r];
            float wh = __expf(-(xh >= 0.f ? xh : ALPHA * xh));
            float wl = __expf(-(xl >= 0.f ? xl : ALPHA * xl));
            wsum_h += wh;
            wsum_l += wl;
            float w = isHigh ? wh : wl;
            float2 f0 = __half22float2(*(__half2*)&v[r].x);
            float2 f1 = __half22float2(*(__half2*)&v[r].y);
            acc.x = fmaf(w, f0.x, acc.x);
            acc.y = fmaf(w, f0.y, acc.y);
            acc.z = fmaf(w, f1.x, acc.z);
            acc.w = fmaf(w, f1.y, acc.w);
        }
    }
    for (; j < end; j++) {
        int d0 = g_csr_dst[j];
        float xh = sh_n - g_s_high[d0];
        float xl = sl_n + g_s_low[d0];
        float wh = __expf(-(xh >= 0.f ? xh : ALPHA * xh));
        float wl = __expf(-(xl >= 0.f ? xl : ALPHA * xl));
        wsum_h += wh;
        wsum_l += wl;
        float w = isHigh ? wh : wl;
        uint2 v = g_Hh[(long)d0 * 32 + lane];
        float2 f0 = __half22float2(*(__half2*)&v.x);
        float2 f1 = __half22float2(*(__half2*)&v.y);
        acc.x = fmaf(w, f0.x, acc.x);
        acc.y = fmaf(w, f0.y, acc.y);
        acc.z = fmaf(w, f1.x, acc.z);
        acc.w = fmaf(w, f1.y, acc.w);
    }

    float wsum = (isHigh ? wsum_h : wsum_l) + 1e-16f;
    float inv = 1.0f / wsum;
    float4 o = make_float4(acc.x * inv, acc.y * inv, acc.z * inv, acc.w * inv);
    *(float4*)&out[(long)warp * D_HID + lane * 4] = o;

    float m = fmaxf(fmaxf(fabsf(o.x), fabsf(o.y)), fmaxf(fabsf(o.z), fabsf(o.w)));
    #pragma unroll
    for (int off = 16; off > 0; off >>= 1)
        m = fmaxf(m, __shfl_down_sync(0xffffffffu, m, off));
    if (lane == 0) atomicMax(&g_t_out, __float_as_uint(m));
}

// ---------------- K7: final relu_bt in place on d_out ----------------
__global__ void k_final(float* __restrict__ out) {
    int i = blockIdx.x * blockDim.x + threadIdx.x;
    if (i >= N_NODES * D_HID) return;
    float t = __uint_as_float(g_t_out);
    float x = out[i];
    float y = x >= 0.f ? x : BT_SLOPE * x;
    out[i] = fminf(y, t);
}

// ---------------- launch: fork edge chain onto a side stream ----------------
extern "C" void kernel_launch(void* const* d_in, const int* in_sizes, int n_in,
                              void* d_out, int out_size) {
    const float* input  = (const float*)d_in[0];
    const int*   e32    = (const int*)d_in[1];     // int32 or int64 (detected)
    const float* W_high = (const float*)d_in[2];
    const float* W_low  = (const float*)d_in[3];
    const float* a_high = (const float*)d_in[4];
    const float* a_low  = (const float*)d_in[5];
    float* out = (float*)d_out;

    // kernel_launch runs exactly twice (correctness + capture); creating one
    // stream + two events per call is deterministic and alloc-free on device.
    cudaStream_t s2;
    cudaEvent_t evFork, evJoin;
    cudaStreamCreateWithFlags(&s2, cudaStreamNonBlocking);
    cudaEventCreateWithFlags(&evFork, cudaEventDisableTiming);
    cudaEventCreateWithFlags(&evJoin, cudaEventDisableTiming);

    k_setup<<<(N_NODES + 255) / 256, 256>>>(e32, W_high, W_low);

    // fork: edge chain on s2
    cudaEventRecord(evFork, 0);
    cudaStreamWaitEvent(s2, evFork, 0);
    k_hist<<<(N_EDGES / 4 + 255) / 256, 256, 0, s2>>>(e32);
    k_scan1<<<NB_SCAN, 1024, 0, s2>>>();
    k_scan2<<<1, 32, 0, s2>>>();
    k_scatter<<<(N_EDGES / 2 + 255) / 256, 256, 0, s2>>>(e32);
    cudaEventRecord(evJoin, s2);

    // node chain on the main stream
    k_gemm<<<(N_NODES + GBM - 1) / GBM, 256>>>(input);
    k_act_s<<<(N_NODES * 32 + 255) / 256, 256>>>(a_high, a_low);

    // join, then aggregate + finalize
    cudaStreamWaitEvent(0, evJoin, 0);
    k_agg<<<(N_NODES * 32 + 255) / 256, 256>>>(out);
    k_final<<<(N_NODES * D_HID + 255) / 256, 256>>>(out);
}

// round 8
// speedup vs baseline: 1.8814x; 1.0823x over previous
#include <cuda_runtime.h>
#include <cuda_fp16.h>
#include <mma.h>
#include <math.h>

using namespace nvcuda;

#define N_NODES 50000
#define N_EDGES 1600000
#define D_IN    256
#define D_OUT   64
#define D_HID   128   // 2*D_OUT, concat layout: [high(0..63) | low(64..127)]

#define ALPHA    0.2f
#define BT_SLOPE 0.01f

#define NB_SCAN 49    // ceil(50000/1024)

// ---------------- scratch (device globals; no cudaMalloc allowed) ----------------
__device__ float g_Wc[D_IN * D_HID];              // combined [256][128] weight, tf32-rounded
__device__ float g_H[(N_NODES + 64) * D_HID];     // fp32 H (+64 pad rows for wmma tail stores)
__device__ uint2 g_Hh[N_NODES * 32];              // fp16 copy: 128 halves/node
__device__ float2 g_s2[N_NODES];                  // (s_high, s_low) per node
__device__ unsigned g_t_high, g_t_low, g_t_out;   // float bits of global abs-max
__device__ int g_hist[N_NODES];
__device__ int g_scan_local[N_NODES];             // inclusive scan within 1024-tile
__device__ int g_blocksum[64];
__device__ int g_blockpref[64];                   // exclusive scan of block sums
__device__ int g_cursor[N_NODES];
__device__ int g_csr_dst[N_EDGES];
__device__ int g_edge_is64;

__device__ __forceinline__ void cp_async16(void* sptr, const void* gptr) {
    unsigned saddr = (unsigned)__cvta_generic_to_shared(sptr);
    asm volatile("cp.async.cg.shared.global [%0], [%1], 16;" :: "r"(saddr), "l"(gptr));
}

// exclusive prefix of hist at i (i in [0, N_NODES])
__device__ __forceinline__ int row_start_at(int i) {
    if (i == 0) return 0;
    int j = i - 1;
    return g_blockpref[j >> 10] + g_scan_local[j];
}

// ---------------- K_setup: detect edge dtype + init + build Wc (tf32-rounded) ----------------
__global__ void k_setup(const int* __restrict__ e32,
                        const float* __restrict__ W_high,
                        const float* __restrict__ W_low) {
    int i = blockIdx.x * blockDim.x + threadIdx.x;
    if (blockIdx.x == 0) {
        int v = e32[2 * threadIdx.x + 1];       // 256 odd words sampled
        int any = __syncthreads_or(v != 0);
        if (threadIdx.x == 0) {
            g_edge_is64 = (any == 0) ? 1 : 0;
            g_t_high = 0u; g_t_low = 0u; g_t_out = 0u;
        }
    }
    if (i < N_NODES) { g_hist[i] = 0; g_cursor[i] = 0; }
    if (i < D_IN * D_HID) {
        int k = i / D_HID;
        int c = i % D_HID;
        float v = (c < D_OUT) ? W_high[k * D_OUT + c] : W_low[k * D_OUT + (c - D_OUT)];
        g_Wc[i] = wmma::__float_to_tf32(v);     // pre-round B once
    }
}

// ---------------- K1: TF32 WMMA GEMM, 3-stage cp.async pipeline ----------------
#define GBM 64
#define GBK 16
#define AS_LD 20
#define BS_LD 132
#define KITERS (D_IN / GBK)
#define NSTAGE 3
__global__ void __launch_bounds__(256, 2) k_gemm(const float* __restrict__ A) {
    __shared__ float As[NSTAGE][GBM][AS_LD];
    __shared__ float Bs[NSTAGE][GBK][BS_LD];
    __shared__ float redH[8], redL[8];

    int tid = threadIdx.x;
    int lane = tid & 31;
    int wid = tid >> 5;
    int warp_row = wid & 3;
    int warp_col = wid >> 2;
    int rowBase = blockIdx.x * GBM;

    wmma::fragment<wmma::accumulator, 16, 16, 8, float> acc[4];
    #pragma unroll
    for (int q = 0; q < 4; q++) wmma::fill_fragment(acc[q], 0.0f);

    int aRow = tid >> 2;
    int aCol = (tid & 3) * 4;
    int bRow = tid >> 4;
    int bCol = (tid & 15) * 8;
    int gr = rowBase + aRow;
    bool aOK = gr < N_NODES;
    const float* aSrc = &A[(long)gr * D_IN + aCol];

    // stage tiles 0 and 1
    #pragma unroll
    for (int p = 0; p < 2; p++) {
        int k0 = p * GBK;
        if (aOK) cp_async16(&As[p][aRow][aCol], aSrc + k0);
        else     *(float4*)&As[p][aRow][aCol] = make_float4(0.f, 0.f, 0.f, 0.f);
        cp_async16(&Bs[p][bRow][bCol],     &g_Wc[(k0 + bRow) * D_HID + bCol]);
        cp_async16(&Bs[p][bRow][bCol + 4], &g_Wc[(k0 + bRow) * D_HID + bCol + 4]);
        asm volatile("cp.async.commit_group;");
    }

    for (int it = 0; it < KITERS; it++) {
        int buf = it % NSTAGE;
        if (it + 2 < KITERS) {
            int k0 = (it + 2) * GBK;
            int nb = (it + 2) % NSTAGE;
            if (aOK) cp_async16(&As[nb][aRow][aCol], aSrc + k0);
            else     *(float4*)&As[nb][aRow][aCol] = make_float4(0.f, 0.f, 0.f, 0.f);
            cp_async16(&Bs[nb][bRow][bCol],     &g_Wc[(k0 + bRow) * D_HID + bCol]);
            cp_async16(&Bs[nb][bRow][bCol + 4], &g_Wc[(k0 + bRow) * D_HID + bCol + 4]);
        }
        asm volatile("cp.async.commit_group;");    // empty group at tail is fine
        asm volatile("cp.async.wait_group 2;");    // tile `it` guaranteed complete
        __syncthreads();

        #pragma unroll
        for (int kk = 0; kk < GBK; kk += 8) {
            wmma::fragment<wmma::matrix_a, 16, 16, 8, wmma::precision::tf32, wmma::row_major> af;
            wmma::load_matrix_sync(af, &As[buf][warp_row * 16][kk], AS_LD);
            #pragma unroll
            for (int i = 0; i < af.num_elements; i++)
                af.x[i] = wmma::__float_to_tf32(af.x[i]);
            #pragma unroll
            for (int q = 0; q < 4; q++) {
                wmma::fragment<wmma::matrix_b, 16, 16, 8, wmma::precision::tf32, wmma::row_major> bf;
                wmma::load_matrix_sync(bf, &Bs[buf][kk][warp_col * 64 + q * 16], BS_LD);
                wmma::mma_sync(acc[q], af, bf, acc[q]);
            }
        }
        __syncthreads();
    }

    int outRow = rowBase + warp_row * 16;
    float m = 0.f;
    #pragma unroll
    for (int q = 0; q < 4; q++) {
        int col = warp_col * 64 + q * 16;
        wmma::store_matrix_sync(&g_H[(long)outRow * D_HID + col], acc[q],
                                D_HID, wmma::mem_row_major);
        #pragma unroll
        for (int i = 0; i < acc[q].num_elements; i++)
            m = fmaxf(m, fabsf(acc[q].x[i]));
    }
    #pragma unroll
    for (int o = 16; o > 0; o >>= 1)
        m = fmaxf(m, __shfl_down_sync(0xffffffffu, m, o));
    if (lane == 0) {
        redH[wid] = (warp_col == 0) ? m : 0.f;
        redL[wid] = (warp_col == 0) ? 0.f : m;
    }
    __syncthreads();
    if (tid == 0) {
        float mh = 0.f, ml = 0.f;
        #pragma unroll
        for (int w = 0; w < 8; w++) { mh = fmaxf(mh, redH[w]); ml = fmaxf(ml, redL[w]); }
        atomicMax(&g_t_high, __float_as_uint(mh));
        atomicMax(&g_t_low,  __float_as_uint(ml));
    }
}

// ---------------- K2: relu_bt in place + fp16 copy + per-node scalars ----------------
__global__ void k_act_s(const float* __restrict__ a_high,
                        const float* __restrict__ a_low) {
    int warp = (blockIdx.x * blockDim.x + threadIdx.x) >> 5;
    int lane = threadIdx.x & 31;
    if (warp >= N_NODES) return;
    bool isHigh = lane < 16;
    float t = __uint_as_float(isHigh ? g_t_high : g_t_low);

    float4 x = *(float4*)&g_H[(long)warp * D_HID + lane * 4];
    float4 y;
    y.x = fminf(x.x >= 0.f ? x.x : BT_SLOPE * x.x, t);
    y.y = fminf(x.y >= 0.f ? x.y : BT_SLOPE * x.y, t);
    y.z = fminf(x.z >= 0.f ? x.z : BT_SLOPE * x.z, t);
    y.w = fminf(x.w >= 0.f ? x.w : BT_SLOPE * x.w, t);
    *(float4*)&g_H[(long)warp * D_HID + lane * 4] = y;

    __half2 p0 = __floats2half2_rn(y.x, y.y);
    __half2 p1 = __floats2half2_rn(y.z, y.w);
    uint2 packed;
    packed.x = *(unsigned*)&p0;
    packed.y = *(unsigned*)&p1;
    g_Hh[warp * 32 + lane] = packed;

    float4 a4 = isHigh ? *(const float4*)&a_high[lane * 4]
                       : *(const float4*)&a_low[(lane - 16) * 4];
    float dot = y.x * a4.x + y.y * a4.y + y.z * a4.z + y.w * a4.w;
    float ph = isHigh ? dot : 0.f;
    float pl = isHigh ? 0.f : dot;
    #pragma unroll
    for (int o = 16; o > 0; o >>= 1) {
        ph += __shfl_down_sync(0xffffffffu, ph, o);
        pl += __shfl_down_sync(0xffffffffu, pl, o);
    }
    if (lane == 0) g_s2[warp] = make_float2(ph, pl);
}

// ---------------- K3: histogram of src, 4 edges/thread ----------------
__global__ void k_hist(const int* __restrict__ e32) {
    int base = (blockIdx.x * blockDim.x + threadIdx.x) * 4;
    if (base >= N_EDGES) return;                    // N_EDGES % 4 == 0
    int s[4];
    if (g_edge_is64) {
        int4 a = *(const int4*)&e32[(long)base * 2];
        int4 b = *(const int4*)&e32[(long)base * 2 + 4];
        s[0] = a.x; s[1] = a.z; s[2] = b.x; s[3] = b.z;
    } else {
        int4 a = *(const int4*)&e32[base];
        s[0] = a.x; s[1] = a.y; s[2] = a.z; s[3] = a.w;
    }
    #pragma unroll
    for (int r = 0; r < 4; r++)
        if ((unsigned)s[r] < (unsigned)N_NODES)
            atomicAdd(&g_hist[s[r]], 1);
}

// ---------------- K4a: per-1024-tile inclusive scan ----------------
__global__ void k_scan1() {
    __shared__ int wsum[32];
    int tid = threadIdx.x, lane = tid & 31, wid = tid >> 5;
    int i = blockIdx.x * 1024 + tid;
    int v = (i < N_NODES) ? g_hist[i] : 0;
    int inc = v;
    #pragma unroll
    for (int o = 1; o < 32; o <<= 1) {
        int tv = __shfl_up_sync(0xffffffffu, inc, o);
        if (lane >= o) inc += tv;
    }
    if (lane == 31) wsum[wid] = inc;
    __syncthreads();
    if (wid == 0) {
        int s = wsum[lane];
        #pragma unroll
        for (int o = 1; o < 32; o <<= 1) {
            int tv = __shfl_up_sync(0xffffffffu, s, o);
            if (lane >= o) s += tv;
        }
        wsum[lane] = s;
    }
    __syncthreads();
    int incl = inc + ((wid == 0) ? 0 : wsum[wid - 1]);
    if (i < N_NODES) g_scan_local[i] = incl;
    if (tid == 1023) g_blocksum[blockIdx.x] = incl;
}

// ---------------- K4b: scan 49 block sums (1 warp, 2 elems/lane) ----------------
__global__ void k_scan2() {
    int lane = threadIdx.x;
    int v0 = (2 * lane < NB_SCAN)     ? g_blocksum[2 * lane]     : 0;
    int v1 = (2 * lane + 1 < NB_SCAN) ? g_blocksum[2 * lane + 1] : 0;
    int p = v0 + v1;
    int inc = p;
    #pragma unroll
    for (int o = 1; o < 32; o <<= 1) {
        int tv = __shfl_up_sync(0xffffffffu, inc, o);
        if (lane >= o) inc += tv;
    }
    int excl = inc - p;
    if (2 * lane < NB_SCAN)     g_blockpref[2 * lane]     = excl;
    if (2 * lane + 1 < NB_SCAN) g_blockpref[2 * lane + 1] = excl + v0;
}

// ---------------- K5: scatter edges into CSR by src, 2 edges/thread ----------------
__global__ void k_scatter(const int* __restrict__ e32) {
    int base = (blockIdx.x * blockDim.x + threadIdx.x) * 2;
    if (base >= N_EDGES) return;                    // N_EDGES % 2 == 0
    int s0, s1, d0, d1;
    if (g_edge_is64) {
        int4 a = *(const int4*)&e32[(long)base * 2];
        int4 b = *(const int4*)&e32[((long)N_EDGES + base) * 2];
        s0 = a.x; s1 = a.z; d0 = b.x; d1 = b.z;
    } else {
        int2 a = *(const int2*)&e32[base];
        int2 b = *(const int2*)&e32[N_EDGES + base];
        s0 = a.x; s1 = a.y; d0 = b.x; d1 = b.y;
    }
    if ((unsigned)s0 < (unsigned)N_NODES) {
        if ((unsigned)d0 >= (unsigned)N_NODES) d0 = 0;
        int pos = row_start_at(s0) + atomicAdd(&g_cursor[s0], 1);
        g_csr_dst[pos] = d0;
    }
    if ((unsigned)s1 < (unsigned)N_NODES) {
        if ((unsigned)d1 >= (unsigned)N_NODES) d1 = 0;
        int pos = row_start_at(s1) + atomicAdd(&g_cursor[s1], 1);
        g_csr_dst[pos] = d1;
    }
}

// ---------------- K6: warp-per-node aggregation, 8-edge unroll ----------------
#define UNROLL_E 8
__global__ void k_agg(float* __restrict__ out) {
    int warp = (blockIdx.x * blockDim.x + threadIdx.x) >> 5;
    int lane = threadIdx.x & 31;
    if (warp >= N_NODES) return;
    bool isHigh = lane < 16;

    int start = row_start_at(warp);
    int end   = row_start_at(warp + 1);
    float2 s_n = g_s2[warp];

    float4 acc = make_float4(0.f, 0.f, 0.f, 0.f);
    float wsum_h = 0.f, wsum_l = 0.f;

    int j = start;
    for (; j + UNROLL_E - 1 < end; j += UNROLL_E) {
        int d[UNROLL_E];
        float2 sd[UNROLL_E];
        uint2 v[UNROLL_E];
        #pragma unroll
        for (int r = 0; r < UNROLL_E; r++) d[r] = g_csr_dst[j + r];
        #pragma unroll
        for (int r = 0; r < UNROLL_E; r++) {
            sd[r] = g_s2[d[r]];
            v[r]  = g_Hh[(long)d[r] * 32 + lane];
        }
        #pragma unroll
        for (int r = 0; r < UNROLL_E; r++) {
            float xh = s_n.x - sd[r].x;
            float xl = s_n.y + sd[r].y;
            float wh = __expf(-(xh >= 0.f ? xh : ALPHA * xh));
            float wl = __expf(-(xl >= 0.f ? xl : ALPHA * xl));
            wsum_h += wh;
            wsum_l += wl;
            float w = isHigh ? wh : wl;
            float2 f0 = __half22float2(*(__half2*)&v[r].x);
            float2 f1 = __half22float2(*(__half2*)&v[r].y);
            acc.x = fmaf(w, f0.x, acc.x);
            acc.y = fmaf(w, f0.y, acc.y);
            acc.z = fmaf(w, f1.x, acc.z);
            acc.w = fmaf(w, f1.y, acc.w);
        }
    }
    for (; j < end; j++) {
        int d0 = g_csr_dst[j];
        float2 sd = g_s2[d0];
        float xh = s_n.x - sd.x;
        float xl = s_n.y + sd.y;
        float wh = __expf(-(xh >= 0.f ? xh : ALPHA * xh));
        float wl = __expf(-(xl >= 0.f ? xl : ALPHA * xl));
        wsum_h += wh;
        wsum_l += wl;
        float w = isHigh ? wh : wl;
        uint2 v = g_Hh[(long)d0 * 32 + lane];
        float2 f0 = __half22float2(*(__half2*)&v.x);
        float2 f1 = __half22float2(*(__half2*)&v.y);
        acc.x = fmaf(w, f0.x, acc.x);
        acc.y = fmaf(w, f0.y, acc.y);
        acc.z = fmaf(w, f1.x, acc.z);
        acc.w = fmaf(w, f1.y, acc.w);
    }

    float wsum = (isHigh ? wsum_h : wsum_l) + 1e-16f;
    float inv = 1.0f / wsum;
    float4 o = make_float4(acc.x * inv, acc.y * inv, acc.z * inv, acc.w * inv);
    *(float4*)&out[(long)warp * D_HID + lane * 4] = o;

    float m = fmaxf(fmaxf(fabsf(o.x), fabsf(o.y)), fmaxf(fabsf(o.z), fabsf(o.w)));
    #pragma unroll
    for (int off = 16; off > 0; off >>= 1)
        m = fmaxf(m, __shfl_down_sync(0xffffffffu, m, off));
    if (lane == 0) atomicMax(&g_t_out, __float_as_uint(m));
}

// ---------------- K7: final relu_bt in place on d_out (float4) ----------------
__global__ void k_final(float* __restrict__ out) {
    int i = blockIdx.x * blockDim.x + threadIdx.x;
    if (i >= N_NODES * D_HID / 4) return;
    float t = __uint_as_float(g_t_out);
    float4 x = *(float4*)&out[i * 4];
    float4 y;
    y.x = fminf(x.x >= 0.f ? x.x : BT_SLOPE * x.x, t);
    y.y = fminf(x.y >= 0.f ? x.y : BT_SLOPE * x.y, t);
    y.z = fminf(x.z >= 0.f ? x.z : BT_SLOPE * x.z, t);
    y.w = fminf(x.w >= 0.f ? x.w : BT_SLOPE * x.w, t);
    *(float4*)&out[i * 4] = y;
}

// ---------------- launch: fork edge chain onto a side stream ----------------
extern "C" void kernel_launch(void* const* d_in, const int* in_sizes, int n_in,
                              void* d_out, int out_size) {
    const float* input  = (const float*)d_in[0];
    const int*   e32    = (const int*)d_in[1];     // int32 or int64 (detected)
    const float* W_high = (const float*)d_in[2];
    const float* W_low  = (const float*)d_in[3];
    const float* a_high = (const float*)d_in[4];
    const float* a_low  = (const float*)d_in[5];
    float* out = (float*)d_out;

    cudaStream_t s2;
    cudaEvent_t evFork, evJoin;
    cudaStreamCreateWithFlags(&s2, cudaStreamNonBlocking);
    cudaEventCreateWithFlags(&evFork, cudaEventDisableTiming);
    cudaEventCreateWithFlags(&evJoin, cudaEventDisableTiming);

    k_setup<<<(N_NODES + 255) / 256, 256>>>(e32, W_high, W_low);

    // fork: edge chain on s2
    cudaEventRecord(evFork, 0);
    cudaStreamWaitEvent(s2, evFork, 0);
    k_hist<<<(N_EDGES / 4 + 255) / 256, 256, 0, s2>>>(e32);
    k_scan1<<<NB_SCAN, 1024, 0, s2>>>();
    k_scan2<<<1, 32, 0, s2>>>();
    k_scatter<<<(N_EDGES / 2 + 255) / 256, 256, 0, s2>>>(e32);
    cudaEventRecord(evJoin, s2);

    // node chain on the main stream
    k_gemm<<<(N_NODES + GBM - 1) / GBM, 256>>>(input);
    k_act_s<<<(N_NODES * 32 + 255) / 256, 256>>>(a_high, a_low);

    // join, then aggregate + finalize
    cudaStreamWaitEvent(0, evJoin, 0);
    k_agg<<<(N_NODES * 32 + 255) / 256, 256>>>(out);
    k_final<<<(N_NODES * D_HID / 4 + 255) / 256, 256>>>(out);
}

// round 10
// speedup vs baseline: 2.1231x; 1.1285x over previous
#include <cuda_runtime.h>
#include <cuda_fp16.h>
#include <mma.h>
#include <math.h>

using namespace nvcuda;

#define N_NODES 50000
#define N_EDGES 1600000
#define D_IN    256
#define D_OUT   64
#define D_HID   128   // 2*D_OUT, concat layout: [high(0..63) | low(64..127)]

#define ALPHA    0.2f
#define BT_SLOPE 0.01f

#define NB_SCAN 49    // ceil(50000/1024)

// ---------------- scratch (device globals; no cudaMalloc allowed) ----------------
__device__ float g_Wc[D_IN * D_HID];              // combined [256][128] weight, tf32-rounded
__device__ float g_H[(N_NODES + 64) * D_HID];     // fp32 H (+64 pad rows for wmma tail stores)
__device__ uint4 g_Hh4[N_NODES * 16];             // fp16 copy: 128 halves/node = 16 uint4
__device__ float2 g_s2[N_NODES];                  // (s_high, s_low) per node
__device__ unsigned g_t_high, g_t_low, g_t_out;   // float bits of global abs-max
__device__ int g_hist[N_NODES];
__device__ int g_scan_local[N_NODES];             // inclusive scan within 1024-tile
__device__ int g_blocksum[64];
__device__ int g_blockpref[64];                   // exclusive scan of block sums
__device__ int g_cursor[N_NODES];
__device__ int g_csr_dst[N_EDGES];
__device__ int g_edge_is64;

__device__ __forceinline__ void cp_async16(void* sptr, const void* gptr) {
    unsigned saddr = (unsigned)__cvta_generic_to_shared(sptr);
    asm volatile("cp.async.cg.shared.global [%0], [%1], 16;" :: "r"(saddr), "l"(gptr));
}

// exclusive prefix of hist at i (i in [0, N_NODES])
__device__ __forceinline__ int row_start_at(int i) {
    if (i == 0) return 0;
    int j = i - 1;
    return g_blockpref[j >> 10] + g_scan_local[j];
}

// ---------------- K_setup: detect edge dtype + init + build Wc (tf32-rounded) ----------------
__global__ void k_setup(const int* __restrict__ e32,
                        const float* __restrict__ W_high,
                        const float* __restrict__ W_low) {
    int i = blockIdx.x * blockDim.x + threadIdx.x;
    if (blockIdx.x == 0) {
        int v = e32[2 * threadIdx.x + 1];       // 256 odd words sampled
        int any = __syncthreads_or(v != 0);
        if (threadIdx.x == 0) {
            g_edge_is64 = (any == 0) ? 1 : 0;
            g_t_high = 0u; g_t_low = 0u; g_t_out = 0u;
        }
    }
    if (i < N_NODES) { g_hist[i] = 0; g_cursor[i] = 0; }
    if (i < D_IN * D_HID) {
        int k = i / D_HID;
        int c = i % D_HID;
        float v = (c < D_OUT) ? W_high[k * D_OUT + c] : W_low[k * D_OUT + (c - D_OUT)];
        g_Wc[i] = wmma::__float_to_tf32(v);     // pre-round B once
    }
}

// ---------------- K1: TF32 WMMA GEMM, 3-stage cp.async pipeline ----------------
#define GBM 64
#define GBK 16
#define AS_LD 20
#define BS_LD 132
#define KITERS (D_IN / GBK)
#define NSTAGE 3
__global__ void __launch_bounds__(256, 2) k_gemm(const float* __restrict__ A) {
    __shared__ float As[NSTAGE][GBM][AS_LD];
    __shared__ float Bs[NSTAGE][GBK][BS_LD];
    __shared__ float redH[8], redL[8];

    int tid = threadIdx.x;
    int lane = tid & 31;
    int wid = tid >> 5;
    int warp_row = wid & 3;
    int warp_col = wid >> 2;
    int rowBase = blockIdx.x * GBM;

    wmma::fragment<wmma::accumulator, 16, 16, 8, float> acc[4];
    #pragma unroll
    for (int q = 0; q < 4; q++) wmma::fill_fragment(acc[q], 0.0f);

    int aRow = tid >> 2;
    int aCol = (tid & 3) * 4;
    int bRow = tid >> 4;
    int bCol = (tid & 15) * 8;
    int gr = rowBase + aRow;
    bool aOK = gr < N_NODES;
    const float* aSrc = &A[(long)gr * D_IN + aCol];

    #pragma unroll
    for (int p = 0; p < 2; p++) {
        int k0 = p * GBK;
        if (aOK) cp_async16(&As[p][aRow][aCol], aSrc + k0);
        else     *(float4*)&As[p][aRow][aCol] = make_float4(0.f, 0.f, 0.f, 0.f);
        cp_async16(&Bs[p][bRow][bCol],     &g_Wc[(k0 + bRow) * D_HID + bCol]);
        cp_async16(&Bs[p][bRow][bCol + 4], &g_Wc[(k0 + bRow) * D_HID + bCol + 4]);
        asm volatile("cp.async.commit_group;");
    }

    for (int it = 0; it < KITERS; it++) {
        int buf = it % NSTAGE;
        if (it + 2 < KITERS) {
            int k0 = (it + 2) * GBK;
            int nb = (it + 2) % NSTAGE;
            if (aOK) cp_async16(&As[nb][aRow][aCol], aSrc + k0);
            else     *(float4*)&As[nb][aRow][aCol] = make_float4(0.f, 0.f, 0.f, 0.f);
            cp_async16(&Bs[nb][bRow][bCol],     &g_Wc[(k0 + bRow) * D_HID + bCol]);
            cp_async16(&Bs[nb][bRow][bCol + 4], &g_Wc[(k0 + bRow) * D_HID + bCol + 4]);
        }
        asm volatile("cp.async.commit_group;");
        asm volatile("cp.async.wait_group 2;");
        __syncthreads();

        #pragma unroll
        for (int kk = 0; kk < GBK; kk += 8) {
            wmma::fragment<wmma::matrix_a, 16, 16, 8, wmma::precision::tf32, wmma::row_major> af;
            wmma::load_matrix_sync(af, &As[buf][warp_row * 16][kk], AS_LD);
            #pragma unroll
            for (int i = 0; i < af.num_elements; i++)
                af.x[i] = wmma::__float_to_tf32(af.x[i]);
            #pragma unroll
            for (int q = 0; q < 4; q++) {
                wmma::fragment<wmma::matrix_b, 16, 16, 8, wmma::precision::tf32, wmma::row_major> bf;
                wmma::load_matrix_sync(bf, &Bs[buf][kk][warp_col * 64 + q * 16], BS_LD);
                wmma::mma_sync(acc[q], af, bf, acc[q]);
            }
        }
        __syncthreads();
    }

    int outRow = rowBase + warp_row * 16;
    float m = 0.f;
    #pragma unroll
    for (int q = 0; q < 4; q++) {
        int col = warp_col * 64 + q * 16;
        wmma::store_matrix_sync(&g_H[(long)outRow * D_HID + col], acc[q],
                                D_HID, wmma::mem_row_major);
        #pragma unroll
        for (int i = 0; i < acc[q].num_elements; i++)
            m = fmaxf(m, fabsf(acc[q].x[i]));
    }
    #pragma unroll
    for (int o = 16; o > 0; o >>= 1)
        m = fmaxf(m, __shfl_down_sync(0xffffffffu, m, o));
    if (lane == 0) {
        redH[wid] = (warp_col == 0) ? m : 0.f;
        redL[wid] = (warp_col == 0) ? 0.f : m;
    }
    __syncthreads();
    if (tid == 0) {
        float mh = 0.f, ml = 0.f;
        #pragma unroll
        for (int w = 0; w < 8; w++) { mh = fmaxf(mh, redH[w]); ml = fmaxf(ml, redL[w]); }
        atomicMax(&g_t_high, __float_as_uint(mh));
        atomicMax(&g_t_low,  __float_as_uint(ml));
    }
}

// ---------------- K2: relu_bt in place + fp16 copy + per-node scalars ----------------
__global__ void k_act_s(const float* __restrict__ a_high,
                        const float* __restrict__ a_low) {
    int warp = (blockIdx.x * blockDim.x + threadIdx.x) >> 5;
    int lane = threadIdx.x & 31;
    if (warp >= N_NODES) return;
    bool isHigh = lane < 16;
    float t = __uint_as_float(isHigh ? g_t_high : g_t_low);

    float4 x = *(float4*)&g_H[(long)warp * D_HID + lane * 4];
    float4 y;
    y.x = fminf(x.x >= 0.f ? x.x : BT_SLOPE * x.x, t);
    y.y = fminf(x.y >= 0.f ? x.y : BT_SLOPE * x.y, t);
    y.z = fminf(x.z >= 0.f ? x.z : BT_SLOPE * x.z, t);
    y.w = fminf(x.w >= 0.f ? x.w : BT_SLOPE * x.w, t);
    *(float4*)&g_H[(long)warp * D_HID + lane * 4] = y;

    __half2 p0 = __floats2half2_rn(y.x, y.y);
    __half2 p1 = __floats2half2_rn(y.z, y.w);
    uint2 packed;
    packed.x = *(unsigned*)&p0;
    packed.y = *(unsigned*)&p1;
    ((uint2*)g_Hh4)[warp * 32 + lane] = packed;

    float4 a4 = isHigh ? *(const float4*)&a_high[lane * 4]
                       : *(const float4*)&a_low[(lane - 16) * 4];
    float dot = y.x * a4.x + y.y * a4.y + y.z * a4.z + y.w * a4.w;
    float ph = isHigh ? dot : 0.f;
    float pl = isHigh ? 0.f : dot;
    #pragma unroll
    for (int o = 16; o > 0; o >>= 1) {
        ph += __shfl_down_sync(0xffffffffu, ph, o);
        pl += __shfl_down_sync(0xffffffffu, pl, o);
    }
    if (lane == 0) g_s2[warp] = make_float2(ph, pl);
}

// ---------------- K3: histogram of src, 4 edges/thread ----------------
__global__ void k_hist(const int* __restrict__ e32) {
    int base = (blockIdx.x * blockDim.x + threadIdx.x) * 4;
    if (base >= N_EDGES) return;                    // N_EDGES % 4 == 0
    int s[4];
    if (g_edge_is64) {
        int4 a = *(const int4*)&e32[(long)base * 2];
        int4 b = *(const int4*)&e32[(long)base * 2 + 4];
        s[0] = a.x; s[1] = a.z; s[2] = b.x; s[3] = b.z;
    } else {
        int4 a = *(const int4*)&e32[base];
        s[0] = a.x; s[1] = a.y; s[2] = a.z; s[3] = a.w;
    }
    #pragma unroll
    for (int r = 0; r < 4; r++)
        if ((unsigned)s[r] < (unsigned)N_NODES)
            atomicAdd(&g_hist[s[r]], 1);
}

// ---------------- K4a: per-1024-tile inclusive scan ----------------
__global__ void k_scan1() {
    __shared__ int wsum[32];
    int tid = threadIdx.x, lane = tid & 31, wid = tid >> 5;
    int i = blockIdx.x * 1024 + tid;
    int v = (i < N_NODES) ? g_hist[i] : 0;
    int inc = v;
    #pragma unroll
    for (int o = 1; o < 32; o <<= 1) {
        int tv = __shfl_up_sync(0xffffffffu, inc, o);
        if (lane >= o) inc += tv;
    }
    if (lane == 31) wsum[wid] = inc;
    __syncthreads();
    if (wid == 0) {
        int s = wsum[lane];
        #pragma unroll
        for (int o = 1; o < 32; o <<= 1) {
            int tv = __shfl_up_sync(0xffffffffu, s, o);
            if (lane >= o) s += tv;
        }
        wsum[lane] = s;
    }
    __syncthreads();
    int incl = inc + ((wid == 0) ? 0 : wsum[wid - 1]);
    if (i < N_NODES) g_scan_local[i] = incl;
    if (tid == 1023) g_blocksum[blockIdx.x] = incl;
}

// ---------------- K4b: scan 49 block sums (1 warp, 2 elems/lane) ----------------
__global__ void k_scan2() {
    int lane = threadIdx.x;
    int v0 = (2 * lane < NB_SCAN)     ? g_blocksum[2 * lane]     : 0;
    int v1 = (2 * lane + 1 < NB_SCAN) ? g_blocksum[2 * lane + 1] : 0;
    int p = v0 + v1;
    int inc = p;
    #pragma unroll
    for (int o = 1; o < 32; o <<= 1) {
        int tv = __shfl_up_sync(0xffffffffu, inc, o);
        if (lane >= o) inc += tv;
    }
    int excl = inc - p;
    if (2 * lane < NB_SCAN)     g_blockpref[2 * lane]     = excl;
    if (2 * lane + 1 < NB_SCAN) g_blockpref[2 * lane + 1] = excl + v0;
}

// ---------------- K5: scatter edges into CSR by src, 2 edges/thread ----------------
__global__ void k_scatter(const int* __restrict__ e32) {
    int base = (blockIdx.x * blockDim.x + threadIdx.x) * 2;
    if (base >= N_EDGES) return;                    // N_EDGES % 2 == 0
    int s0, s1, d0, d1;
    if (g_edge_is64) {
        int4 a = *(const int4*)&e32[(long)base * 2];
        int4 b = *(const int4*)&e32[((long)N_EDGES + base) * 2];
        s0 = a.x; s1 = a.z; d0 = b.x; d1 = b.z;
    } else {
        int2 a = *(const int2*)&e32[base];
        int2 b = *(const int2*)&e32[N_EDGES + base];
        s0 = a.x; s1 = a.y; d0 = b.x; d1 = b.y;
    }
    if ((unsigned)s0 < (unsigned)N_NODES) {
        if ((unsigned)d0 >= (unsigned)N_NODES) d0 = 0;
        int pos = row_start_at(s0) + atomicAdd(&g_cursor[s0], 1);
        g_csr_dst[pos] = d0;
    }
    if ((unsigned)s1 < (unsigned)N_NODES) {
        if ((unsigned)d1 >= (unsigned)N_NODES) d1 = 0;
        int pos = row_start_at(s1) + atomicAdd(&g_cursor[s1], 1);
        g_csr_dst[pos] = d1;
    }
}

// ---------------- K6: half-warp-per-edge aggregation, uint4 gathers ----------------
// lane = half*16 + sub. half-warp `half` owns edge slot (j + half).
// lane covers 8 output halves: cols [sub*8, sub*8+8). sub<8 -> high half, else low.
#define PAIR_UNROLL 4
__global__ void k_agg(float* __restrict__ out) {
    int warp = (blockIdx.x * blockDim.x + threadIdx.x) >> 5;
    int lane = threadIdx.x & 31;
    if (warp >= N_NODES) return;
    int half = lane >> 4;
    int sub  = lane & 15;
    bool hiCols = sub < 8;

    int start = row_start_at(warp);
    int end   = row_start_at(warp + 1);
    float2 s_n = g_s2[warp];

    float acc[8];
    #pragma unroll
    for (int i = 0; i < 8; i++) acc[i] = 0.f;
    float wsum = 0.f;

    int j = start;
    // 4 pairs = 8 edges in flight
    for (; j + 2 * PAIR_UNROLL - 1 < end; j += 2 * PAIR_UNROLL) {
        int d[PAIR_UNROLL];
        float2 sd[PAIR_UNROLL];
        uint4 v[PAIR_UNROLL];
        #pragma unroll
        for (int r = 0; r < PAIR_UNROLL; r++)
            d[r] = g_csr_dst[j + 2 * r + half];      // scalar load, always aligned
        #pragma unroll
        for (int r = 0; r < PAIR_UNROLL; r++) {
            sd[r] = g_s2[d[r]];
            v[r]  = g_Hh4[(long)d[r] * 16 + sub];
        }
        #pragma unroll
        for (int r = 0; r < PAIR_UNROLL; r++) {
            float x = hiCols ? (s_n.x - sd[r].x) : (s_n.y + sd[r].y);
            float w = __expf(-(x >= 0.f ? x : ALPHA * x));
            wsum += w;
            float2 f0 = __half22float2(*(__half2*)&v[r].x);
            float2 f1 = __half22float2(*(__half2*)&v[r].y);
            float2 f2 = __half22float2(*(__half2*)&v[r].z);
            float2 f3 = __half22float2(*(__half2*)&v[r].w);
            acc[0] = fmaf(w, f0.x, acc[0]);
            acc[1] = fmaf(w, f0.y, acc[1]);
            acc[2] = fmaf(w, f1.x, acc[2]);
            acc[3] = fmaf(w, f1.y, acc[3]);
            acc[4] = fmaf(w, f2.x, acc[4]);
            acc[5] = fmaf(w, f2.y, acc[5]);
            acc[6] = fmaf(w, f3.x, acc[6]);
            acc[7] = fmaf(w, f3.y, acc[7]);
        }
    }
    // pair tail
    for (; j + 1 < end; j += 2) {
        int d = g_csr_dst[j + half];
        float2 sd = g_s2[d];
        uint4 v = g_Hh4[(long)d * 16 + sub];
        float x = hiCols ? (s_n.x - sd.x) : (s_n.y + sd.y);
        float w = __expf(-(x >= 0.f ? x : ALPHA * x));
        wsum += w;
        float2 f0 = __half22float2(*(__half2*)&v.x);
        float2 f1 = __half22float2(*(__half2*)&v.y);
        float2 f2 = __half22float2(*(__half2*)&v.z);
        float2 f3 = __half22float2(*(__half2*)&v.w);
        acc[0] = fmaf(w, f0.x, acc[0]);
        acc[1] = fmaf(w, f0.y, acc[1]);
        acc[2] = fmaf(w, f1.x, acc[2]);
        acc[3] = fmaf(w, f1.y, acc[3]);
        acc[4] = fmaf(w, f2.x, acc[4]);
        acc[5] = fmaf(w, f2.y, acc[5]);
        acc[6] = fmaf(w, f3.x, acc[6]);
        acc[7] = fmaf(w, f3.y, acc[7]);
    }
    // single-edge tail: slot 0 only
    if (j < end) {
        int d = g_csr_dst[j];
        float2 sd = g_s2[d];
        uint4 v = g_Hh4[(long)d * 16 + sub];
        float x = hiCols ? (s_n.x - sd.x) : (s_n.y + sd.y);
        float w = __expf(-(x >= 0.f ? x : ALPHA * x));
        if (half) w = 0.f;
        wsum += w;
        float2 f0 = __half22float2(*(__half2*)&v.x);
        float2 f1 = __half22float2(*(__half2*)&v.y);
        float2 f2 = __half22float2(*(__half2*)&v.z);
        float2 f3 = __half22float2(*(__half2*)&v.w);
        acc[0] = fmaf(w, f0.x, acc[0]);
        acc[1] = fmaf(w, f0.y, acc[1]);
        acc[2] = fmaf(w, f1.x, acc[2]);
        acc[3] = fmaf(w, f1.y, acc[3]);
        acc[4] = fmaf(w, f2.x, acc[4]);
        acc[5] = fmaf(w, f2.y, acc[5]);
        acc[6] = fmaf(w, f3.x, acc[6]);
        acc[7] = fmaf(w, f3.y, acc[7]);
    }

    // combine the two edge slots (lane <-> lane^16)
    #pragma unroll
    for (int i = 0; i < 8; i++)
        acc[i] += __shfl_xor_sync(0xffffffffu, acc[i], 16);
    wsum += __shfl_xor_sync(0xffffffffu, wsum, 16);

    float inv = 1.0f / (wsum + 1e-16f);
    float o[8];
    float m = 0.f;
    #pragma unroll
    for (int i = 0; i < 8; i++) {
        o[i] = acc[i] * inv;
        m = fmaxf(m, fabsf(o[i]));
    }
    if (lane < 16) {
        float4 o0 = make_float4(o[0], o[1], o[2], o[3]);
        float4 o1 = make_float4(o[4], o[5], o[6], o[7]);
        *(float4*)&out[(long)warp * D_HID + sub * 8]     = o0;
        *(float4*)&out[(long)warp * D_HID + sub * 8 + 4] = o1;
    }
    #pragma unroll
    for (int off = 16; off > 0; off >>= 1)
        m = fmaxf(m, __shfl_down_sync(0xffffffffu, m, off));
    if (lane == 0) atomicMax(&g_t_out, __float_as_uint(m));
}

// ---------------- K7: final relu_bt in place on d_out (float4) ----------------
__global__ void k_final(float* __restrict__ out) {
    int i = blockIdx.x * blockDim.x + threadIdx.x;
    if (i >= N_NODES * D_HID / 4) return;
    float t = __uint_as_float(g_t_out);
    float4 x = *(float4*)&out[i * 4];
    float4 y;
    y.x = fminf(x.x >= 0.f ? x.x : BT_SLOPE * x.x, t);
    y.y = fminf(x.y >= 0.f ? x.y : BT_SLOPE * x.y, t);
    y.z = fminf(x.z >= 0.f ? x.z : BT_SLOPE * x.z, t);
    y.w = fminf(x.w >= 0.f ? x.w : BT_SLOPE * x.w, t);
    *(float4*)&out[i * 4] = y;
}

// ---------------- launch: fork edge chain onto a side stream ----------------
extern "C" void kernel_launch(void* const* d_in, const int* in_sizes, int n_in,
                              void* d_out, int out_size) {
    const float* input  = (const float*)d_in[0];
    const int*   e32    = (const int*)d_in[1];     // int32 or int64 (detected)
    const float* W_high = (const float*)d_in[2];
    const float* W_low  = (const float*)d_in[3];
    const float* a_high = (const float*)d_in[4];
    const float* a_low  = (const float*)d_in[5];
    float* out = (float*)d_out;

    cudaStream_t s2;
    cudaEvent_t evFork, evJoin;
    cudaStreamCreateWithFlags(&s2, cudaStreamNonBlocking);
    cudaEventCreateWithFlags(&evFork, cudaEventDisableTiming);
    cudaEventCreateWithFlags(&evJoin, cudaEventDisableTiming);

    k_setup<<<(N_NODES + 255) / 256, 256>>>(e32, W_high, W_low);

    // fork: edge chain on s2
    cudaEventRecord(evFork, 0);
    cudaStreamWaitEvent(s2, evFork, 0);
    k_hist<<<(N_EDGES / 4 + 255) / 256, 256, 0, s2>>>(e32);
    k_scan1<<<NB_SCAN, 1024, 0, s2>>>();
    k_scan2<<<1, 32, 0, s2>>>();
    k_scatter<<<(N_EDGES / 2 + 255) / 256, 256, 0, s2>>>(e32);
    cudaEventRecord(evJoin, s2);

    // node chain on the main stream
    k_gemm<<<(N_NODES + GBM - 1) / GBM, 256>>>(input);
    k_act_s<<<(N_NODES * 32 + 255) / 256, 256>>>(a_high, a_low);

    // join, then aggregate + finalize
    cudaStreamWaitEvent(0, evJoin, 0);
    k_agg<<<(N_NODES * 32 + 255) / 256, 256>>>(out);
    k_final<<<(N_NODES * D_HID / 4 + 255) / 256, 256>>>(out);
}

// round 11
// speedup vs baseline: 2.2898x; 1.0785x over previous
#include <cuda_runtime.h>
#include <cuda_fp16.h>
#include <mma.h>
#include <math.h>

using namespace nvcuda;

#define N_NODES 50000
#define N_EDGES 1600000
#define D_IN    256
#define D_OUT   64
#define D_HID   128   // 2*D_OUT, concat layout: [high(0..63) | low(64..127)]

#define ALPHA    0.2f
#define BT_SLOPE 0.01f

#define NB_SCAN 49    // ceil(50000/1024)

// ---------------- scratch (device globals; no cudaMalloc allowed) ----------------
__device__ float g_Wc[D_IN * D_HID];              // combined [256][128] weight, tf32-rounded
__device__ uint4 g_Hh4[N_NODES * 16];             // fp16 activated H: 128 halves/node = 16 uint4
__device__ float2 g_s2[N_NODES];                  // (s_high, s_low) per node
__device__ int g_hist[N_NODES];
__device__ int g_scan_local[N_NODES];             // inclusive scan within 1024-tile
__device__ int g_blocksum[64];
__device__ int g_blockpref[64];                   // exclusive scan of block sums
__device__ int g_cursor[N_NODES];
__device__ int g_csr_dst[N_EDGES];
__device__ int g_edge_is64;

__device__ __forceinline__ void cp_async16(void* sptr, const void* gptr) {
    unsigned saddr = (unsigned)__cvta_generic_to_shared(sptr);
    asm volatile("cp.async.cg.shared.global [%0], [%1], 16;" :: "r"(saddr), "l"(gptr));
}

// exclusive prefix of hist at i (i in [0, N_NODES])
__device__ __forceinline__ int row_start_at(int i) {
    if (i == 0) return 0;
    int j = i - 1;
    return g_blockpref[j >> 10] + g_scan_local[j];
}

// ---------------- K_setup: detect edge dtype + init + build Wc (tf32-rounded) ----------------
__global__ void k_setup(const int* __restrict__ e32,
                        const float* __restrict__ W_high,
                        const float* __restrict__ W_low) {
    int i = blockIdx.x * blockDim.x + threadIdx.x;
    if (blockIdx.x == 0) {
        int v = e32[2 * threadIdx.x + 1];       // 256 odd words sampled
        int any = __syncthreads_or(v != 0);
        if (threadIdx.x == 0) g_edge_is64 = (any == 0) ? 1 : 0;
    }
    if (i < N_NODES) { g_hist[i] = 0; g_cursor[i] = 0; }
    if (i < D_IN * D_HID) {
        int k = i / D_HID;
        int c = i % D_HID;
        float v = (c < D_OUT) ? W_high[k * D_OUT + c] : W_low[k * D_OUT + (c - D_OUT)];
        g_Wc[i] = wmma::__float_to_tf32(v);     // pre-round B once
    }
}

// ---------------- K1: TF32 WMMA GEMM + fused leaky_relu + fp16 pack + s-dot ----------------
#define GBM 64
#define GBK 16
#define AS_LD 20
#define BS_LD 132
#define STG_LD 132   // staging: 64 x 132 floats (528B rows, 16B aligned)
#define KITERS (D_IN / GBK)
#define NSTAGE 3
#define POOL_FLOATS (NSTAGE * GBM * AS_LD + NSTAGE * GBK * BS_LD)   // 10176 >= 64*132=8448
__global__ void __launch_bounds__(256, 2) k_gemm(const float* __restrict__ A,
                                                 const float* __restrict__ a_high,
                                                 const float* __restrict__ a_low) {
    __shared__ float pool[POOL_FLOATS];
    float (*As)[GBM][AS_LD] = (float(*)[GBM][AS_LD])pool;
    float (*Bs)[GBK][BS_LD] = (float(*)[GBK][BS_LD])(pool + NSTAGE * GBM * AS_LD);

    int tid = threadIdx.x;
    int wid = tid >> 5;
    int warp_row = wid & 3;
    int warp_col = wid >> 2;
    int rowBase = blockIdx.x * GBM;

    wmma::fragment<wmma::accumulator, 16, 16, 8, float> acc[4];
    #pragma unroll
    for (int q = 0; q < 4; q++) wmma::fill_fragment(acc[q], 0.0f);

    int aRow = tid >> 2;
    int aCol = (tid & 3) * 4;
    int bRow = tid >> 4;
    int bCol = (tid & 15) * 8;
    int gr = rowBase + aRow;
    bool aOK = gr < N_NODES;
    const float* aSrc = &A[(long)gr * D_IN + aCol];

    #pragma unroll
    for (int p = 0; p < 2; p++) {
        int k0 = p * GBK;
        if (aOK) cp_async16(&As[p][aRow][aCol], aSrc + k0);
        else     *(float4*)&As[p][aRow][aCol] = make_float4(0.f, 0.f, 0.f, 0.f);
        cp_async16(&Bs[p][bRow][bCol],     &g_Wc[(k0 + bRow) * D_HID + bCol]);
        cp_async16(&Bs[p][bRow][bCol + 4], &g_Wc[(k0 + bRow) * D_HID + bCol + 4]);
        asm volatile("cp.async.commit_group;");
    }

    for (int it = 0; it < KITERS; it++) {
        int buf = it % NSTAGE;
        if (it + 2 < KITERS) {
            int k0 = (it + 2) * GBK;
            int nb = (it + 2) % NSTAGE;
            if (aOK) cp_async16(&As[nb][aRow][aCol], aSrc + k0);
            else     *(float4*)&As[nb][aRow][aCol] = make_float4(0.f, 0.f, 0.f, 0.f);
            cp_async16(&Bs[nb][bRow][bCol],     &g_Wc[(k0 + bRow) * D_HID + bCol]);
            cp_async16(&Bs[nb][bRow][bCol + 4], &g_Wc[(k0 + bRow) * D_HID + bCol + 4]);
        }
        asm volatile("cp.async.commit_group;");
        asm volatile("cp.async.wait_group 2;");
        __syncthreads();

        #pragma unroll
        for (int kk = 0; kk < GBK; kk += 8) {
            wmma::fragment<wmma::matrix_a, 16, 16, 8, wmma::precision::tf32, wmma::row_major> af;
            wmma::load_matrix_sync(af, &As[buf][warp_row * 16][kk], AS_LD);
            #pragma unroll
            for (int i = 0; i < af.num_elements; i++)
                af.x[i] = wmma::__float_to_tf32(af.x[i]);
            #pragma unroll
            for (int q = 0; q < 4; q++) {
                wmma::fragment<wmma::matrix_b, 16, 16, 8, wmma::precision::tf32, wmma::row_major> bf;
                wmma::load_matrix_sync(bf, &Bs[buf][kk][warp_col * 64 + q * 16], BS_LD);
                wmma::mma_sync(acc[q], af, bf, acc[q]);
            }
        }
        __syncthreads();
    }

    // ---- fused epilogue: leaky_relu on fragments (relu_bt min is a no-op) ----
    #pragma unroll
    for (int q = 0; q < 4; q++)
        #pragma unroll
        for (int i = 0; i < acc[q].num_elements; i++) {
            float x = acc[q].x[i];
            acc[q].x[i] = x >= 0.f ? x : BT_SLOPE * x;
        }

    // stage activated tile into reused pipeline smem
    float* stage = pool;    // 64 x STG_LD
    #pragma unroll
    for (int q = 0; q < 4; q++)
        wmma::store_matrix_sync(stage + (warp_row * 16) * STG_LD + warp_col * 64 + q * 16,
                                acc[q], STG_LD, wmma::mem_row_major);
    __syncthreads();

    // fp16 pack + s-dot. thread = (row r = tid>>2, quarter q = tid&3), 32 cols each.
    {
        int r = tid >> 2;
        int q = tid & 3;
        int gr2 = rowBase + r;
        const float* rowp = stage + r * STG_LD + q * 32;
        const float* aseg = (q < 2) ? (a_high + (q & 1) * 32) : (a_low + (q & 1) * 32);
        bool valid = gr2 < N_NODES;      // OOB rows are zeros in stage; reads are safe
        float dot = 0.f;
        #pragma unroll
        for (int b = 0; b < 4; b++) {    // 8 floats -> one uint4 (8 halves)
            float4 f0 = *(const float4*)&rowp[b * 8];
            float4 f1 = *(const float4*)&rowp[b * 8 + 4];
            __half2 h0 = __floats2half2_rn(f0.x, f0.y);
            __half2 h1 = __floats2half2_rn(f0.z, f0.w);
            __half2 h2 = __floats2half2_rn(f1.x, f1.y);
            __half2 h3 = __floats2half2_rn(f1.z, f1.w);
            uint4 u;
            u.x = *(unsigned*)&h0;
            u.y = *(unsigned*)&h1;
            u.z = *(unsigned*)&h2;
            u.w = *(unsigned*)&h3;
            if (valid) g_Hh4[(long)gr2 * 16 + q * 4 + b] = u;
            dot += f0.x * aseg[b * 8 + 0] + f0.y * aseg[b * 8 + 1]
                 + f0.z * aseg[b * 8 + 2] + f0.w * aseg[b * 8 + 3]
                 + f1.x * aseg[b * 8 + 4] + f1.y * aseg[b * 8 + 5]
                 + f1.z * aseg[b * 8 + 6] + f1.w * aseg[b * 8 + 7];
        }
        // combine quarters: q0+q1 -> s_high, q2+q3 -> s_low (shfls outside guards)
        float v = dot + __shfl_down_sync(0xffffffffu, dot, 1);
        float slow = __shfl_down_sync(0xffffffffu, v, 2);
        if (q == 0 && valid) g_s2[gr2] = make_float2(v, slow);
    }
}

// ---------------- K3: histogram of src, 4 edges/thread ----------------
__global__ void k_hist(const int* __restrict__ e32) {
    int base = (blockIdx.x * blockDim.x + threadIdx.x) * 4;
    if (base >= N_EDGES) return;                    // N_EDGES % 4 == 0
    int s[4];
    if (g_edge_is64) {
        int4 a = *(const int4*)&e32[(long)base * 2];
        int4 b = *(const int4*)&e32[(long)base * 2 + 4];
        s[0] = a.x; s[1] = a.z; s[2] = b.x; s[3] = b.z;
    } else {
        int4 a = *(const int4*)&e32[base];
        s[0] = a.x; s[1] = a.y; s[2] = a.z; s[3] = a.w;
    }
    #pragma unroll
    for (int r = 0; r < 4; r++)
        if ((unsigned)s[r] < (unsigned)N_NODES)
            atomicAdd(&g_hist[s[r]], 1);
}

// ---------------- K4a: per-1024-tile inclusive scan ----------------
__global__ void k_scan1() {
    __shared__ int wsum[32];
    int tid = threadIdx.x, lane = tid & 31, wid = tid >> 5;
    int i = blockIdx.x * 1024 + tid;
    int v = (i < N_NODES) ? g_hist[i] : 0;
    int inc = v;
    #pragma unroll
    for (int o = 1; o < 32; o <<= 1) {
        int tv = __shfl_up_sync(0xffffffffu, inc, o);
        if (lane >= o) inc += tv;
    }
    if (lane == 31) wsum[wid] = inc;
    __syncthreads();
    if (wid == 0) {
        int s = wsum[lane];
        #pragma unroll
        for (int o = 1; o < 32; o <<= 1) {
            int tv = __shfl_up_sync(0xffffffffu, s, o);
            if (lane >= o) s += tv;
        }
        wsum[lane] = s;
    }
    __syncthreads();
    int incl = inc + ((wid == 0) ? 0 : wsum[wid - 1]);
    if (i < N_NODES) g_scan_local[i] = incl;
    if (tid == 1023) g_blocksum[blockIdx.x] = incl;
}

// ---------------- K4b: scan 49 block sums (1 warp, 2 elems/lane) ----------------
__global__ void k_scan2() {
    int lane = threadIdx.x;
    int v0 = (2 * lane < NB_SCAN)     ? g_blocksum[2 * lane]     : 0;
    int v1 = (2 * lane + 1 < NB_SCAN) ? g_blocksum[2 * lane + 1] : 0;
    int p = v0 + v1;
    int inc = p;
    #pragma unroll
    for (int o = 1; o < 32; o <<= 1) {
        int tv = __shfl_up_sync(0xffffffffu, inc, o);
        if (lane >= o) inc += tv;
    }
    int excl = inc - p;
    if (2 * lane < NB_SCAN)     g_blockpref[2 * lane]     = excl;
    if (2 * lane + 1 < NB_SCAN) g_blockpref[2 * lane + 1] = excl + v0;
}

// ---------------- K5: scatter edges into CSR by src, 2 edges/thread ----------------
__global__ void k_scatter(const int* __restrict__ e32) {
    int base = (blockIdx.x * blockDim.x + threadIdx.x) * 2;
    if (base >= N_EDGES) return;                    // N_EDGES % 2 == 0
    int s0, s1, d0, d1;
    if (g_edge_is64) {
        int4 a = *(const int4*)&e32[(long)base * 2];
        int4 b = *(const int4*)&e32[((long)N_EDGES + base) * 2];
        s0 = a.x; s1 = a.z; d0 = b.x; d1 = b.z;
    } else {
        int2 a = *(const int2*)&e32[base];
        int2 b = *(const int2*)&e32[N_EDGES + base];
        s0 = a.x; s1 = a.y; d0 = b.x; d1 = b.y;
    }
    if ((unsigned)s0 < (unsigned)N_NODES) {
        if ((unsigned)d0 >= (unsigned)N_NODES) d0 = 0;
        int pos = row_start_at(s0) + atomicAdd(&g_cursor[s0], 1);
        g_csr_dst[pos] = d0;
    }
    if ((unsigned)s1 < (unsigned)N_NODES) {
        if ((unsigned)d1 >= (unsigned)N_NODES) d1 = 0;
        int pos = row_start_at(s1) + atomicAdd(&g_cursor[s1], 1);
        g_csr_dst[pos] = d1;
    }
}

// ---------------- K6: half-warp-per-edge aggregation + fused final leaky_relu ----------------
// lane = half*16 + sub. half-warp `half` owns edge slot (j + half).
// lane covers 8 output halves: cols [sub*8, sub*8+8). sub<8 -> high half, else low.
#define PAIR_UNROLL 4
__global__ void k_agg(float* __restrict__ out) {
    int warp = (blockIdx.x * blockDim.x + threadIdx.x) >> 5;
    int lane = threadIdx.x & 31;
    if (warp >= N_NODES) return;
    int half = lane >> 4;
    int sub  = lane & 15;
    bool hiCols = sub < 8;

    int start = row_start_at(warp);
    int end   = row_start_at(warp + 1);
    float2 s_n = g_s2[warp];

    float acc[8];
    #pragma unroll
    for (int i = 0; i < 8; i++) acc[i] = 0.f;
    float wsum = 0.f;

    int j = start;
    for (; j + 2 * PAIR_UNROLL - 1 < end; j += 2 * PAIR_UNROLL) {
        int d[PAIR_UNROLL];
        float2 sd[PAIR_UNROLL];
        uint4 v[PAIR_UNROLL];
        #pragma unroll
        for (int r = 0; r < PAIR_UNROLL; r++)
            d[r] = g_csr_dst[j + 2 * r + half];      // scalar load, always aligned
        #pragma unroll
        for (int r = 0; r < PAIR_UNROLL; r++) {
            sd[r] = g_s2[d[r]];
            v[r]  = g_Hh4[(long)d[r] * 16 + sub];
        }
        #pragma unroll
        for (int r = 0; r < PAIR_UNROLL; r++) {
            float x = hiCols ? (s_n.x - sd[r].x) : (s_n.y + sd[r].y);
            float w = __expf(-(x >= 0.f ? x : ALPHA * x));
            wsum += w;
            float2 f0 = __half22float2(*(__half2*)&v[r].x);
            float2 f1 = __half22float2(*(__half2*)&v[r].y);
            float2 f2 = __half22float2(*(__half2*)&v[r].z);
            float2 f3 = __half22float2(*(__half2*)&v[r].w);
            acc[0] = fmaf(w, f0.x, acc[0]);
            acc[1] = fmaf(w, f0.y, acc[1]);
            acc[2] = fmaf(w, f1.x, acc[2]);
            acc[3] = fmaf(w, f1.y, acc[3]);
            acc[4] = fmaf(w, f2.x, acc[4]);
            acc[5] = fmaf(w, f2.y, acc[5]);
            acc[6] = fmaf(w, f3.x, acc[6]);
            acc[7] = fmaf(w, f3.y, acc[7]);
        }
    }
    for (; j + 1 < end; j += 2) {
        int d = g_csr_dst[j + half];
        float2 sd = g_s2[d];
        uint4 v = g_Hh4[(long)d * 16 + sub];
        float x = hiCols ? (s_n.x - sd.x) : (s_n.y + sd.y);
        float w = __expf(-(x >= 0.f ? x : ALPHA * x));
        wsum += w;
        float2 f0 = __half22float2(*(__half2*)&v.x);
        float2 f1 = __half22float2(*(__half2*)&v.y);
        float2 f2 = __half22float2(*(__half2*)&v.z);
        float2 f3 = __half22float2(*(__half2*)&v.w);
        acc[0] = fmaf(w, f0.x, acc[0]);
        acc[1] = fmaf(w, f0.y, acc[1]);
        acc[2] = fmaf(w, f1.x, acc[2]);
        acc[3] = fmaf(w, f1.y, acc[3]);
        acc[4] = fmaf(w, f2.x, acc[4]);
        acc[5] = fmaf(w, f2.y, acc[5]);
        acc[6] = fmaf(w, f3.x, acc[6]);
        acc[7] = fmaf(w, f3.y, acc[7]);
    }
    if (j < end) {
        int d = g_csr_dst[j];
        float2 sd = g_s2[d];
        uint4 v = g_Hh4[(long)d * 16 + sub];
        float x = hiCols ? (s_n.x - sd.x) : (s_n.y + sd.y);
        float w = __expf(-(x >= 0.f ? x : ALPHA * x));
        if (half) w = 0.f;
        wsum += w;
        float2 f0 = __half22float2(*(__half2*)&v.x);
        float2 f1 = __half22float2(*(__half2*)&v.y);
        float2 f2 = __half22float2(*(__half2*)&v.z);
        float2 f3 = __half22float2(*(__half2*)&v.w);
        acc[0] = fmaf(w, f0.x, acc[0]);
        acc[1] = fmaf(w, f0.y, acc[1]);
        acc[2] = fmaf(w, f1.x, acc[2]);
        acc[3] = fmaf(w, f1.y, acc[3]);
        acc[4] = fmaf(w, f2.x, acc[4]);
        acc[5] = fmaf(w, f2.y, acc[5]);
        acc[6] = fmaf(w, f3.x, acc[6]);
        acc[7] = fmaf(w, f3.y, acc[7]);
    }

    // combine the two edge slots (lane <-> lane^16)
    #pragma unroll
    for (int i = 0; i < 8; i++)
        acc[i] += __shfl_xor_sync(0xffffffffu, acc[i], 16);
    wsum += __shfl_xor_sync(0xffffffffu, wsum, 16);

    if (lane < 16) {
        float inv = 1.0f / (wsum + 1e-16f);
        float o[8];
        #pragma unroll
        for (int i = 0; i < 8; i++) {
            float x = acc[i] * inv;
            o[i] = x >= 0.f ? x : BT_SLOPE * x;   // final relu_bt == leaky_relu
        }
        float4 o0 = make_float4(o[0], o[1], o[2], o[3]);
        float4 o1 = make_float4(o[4], o[5], o[6], o[7]);
        *(float4*)&out[(long)warp * D_HID + sub * 8]     = o0;
        *(float4*)&out[(long)warp * D_HID + sub * 8 + 4] = o1;
    }
}

// ---------------- launch: fork edge chain onto a side stream ----------------
extern "C" void kernel_launch(void* const* d_in, const int* in_sizes, int n_in,
                              void* d_out, int out_size) {
    const float* input  = (const float*)d_in[0];
    const int*   e32    = (const int*)d_in[1];     // int32 or int64 (detected)
    const float* W_high = (const float*)d_in[2];
    const float* W_low  = (const float*)d_in[3];
    const float* a_high = (const float*)d_in[4];
    const float* a_low  = (const float*)d_in[5];
    float* out = (float*)d_out;

    cudaStream_t s2;
    cudaEvent_t evFork, evJoin;
    cudaStreamCreateWithFlags(&s2, cudaStreamNonBlocking);
    cudaEventCreateWithFlags(&evFork, cudaEventDisableTiming);
    cudaEventCreateWithFlags(&evJoin, cudaEventDisableTiming);

    k_setup<<<(N_NODES + 255) / 256, 256>>>(e32, W_high, W_low);

    // fork: edge chain on s2
    cudaEventRecord(evFork, 0);
    cudaStreamWaitEvent(s2, evFork, 0);
    k_hist<<<(N_EDGES / 4 + 255) / 256, 256, 0, s2>>>(e32);
    k_scan1<<<NB_SCAN, 1024, 0, s2>>>();
    k_scan2<<<1, 32, 0, s2>>>();
    k_scatter<<<(N_EDGES / 2 + 255) / 256, 256, 0, s2>>>(e32);
    cudaEventRecord(evJoin, s2);

    // node chain on the main stream: single fused GEMM kernel
    k_gemm<<<(N_NODES + GBM - 1) / GBM, 256>>>(input, a_high, a_low);

    // join, then aggregate (final activation fused)
    cudaStreamWaitEvent(0, evJoin, 0);
    k_agg<<<(N_NODES * 32 + 255) / 256, 256>>>(out);
}